// round 12
// baseline (speedup 1.0000x reference)
#include <cuda_runtime.h>
#include <cstdint>

#define NQMAX 8192
#define DIM   256
#define NB    64
#define SCALE 0.0625f   /* 1/sqrt(256) exactly */

// ---------------- scratch (device globals: allocation-free) ----------------
__device__ float g_Q[NQMAX * DIM];
__device__ float g_K[NQMAX * DIM];
__device__ float g_V[NQMAX * DIM];
__device__ float g_O[NQMAX * DIM];
__device__ int   g_qseg[NB + 1];
__device__ int   g_kseg[NB + 1];

// ---------------- tf32 / mma helpers ---------------------------------------
__device__ __forceinline__ unsigned f2tf32(float x) {
    unsigned r;
    asm("cvt.rna.tf32.f32 %0, %1;" : "=r"(r) : "f"(x));
    return r;
}
__device__ __forceinline__ void split_tf32(float x, unsigned& hi, unsigned& lo) {
    hi = f2tf32(x);
    lo = f2tf32(x - __uint_as_float(hi));
}
__device__ __forceinline__ void mma_tf32(float* d, const unsigned* a, const unsigned* b) {
    asm volatile(
        "mma.sync.aligned.m16n8k8.row.col.f32.tf32.tf32.f32 "
        "{%0,%1,%2,%3}, {%4,%5,%6,%7}, {%8,%9}, {%0,%1,%2,%3};\n"
        : "+f"(d[0]), "+f"(d[1]), "+f"(d[2]), "+f"(d[3])
        : "r"(a[0]), "r"(a[1]), "r"(a[2]), "r"(a[3]), "r"(b[0]), "r"(b[1]));
}
__device__ __forceinline__ void cp16z(void* s, const void* g, bool p) {
    unsigned sa = (unsigned)__cvta_generic_to_shared(s);
    int sz = p ? 16 : 0;
    asm volatile("cp.async.cg.shared.global [%0], [%1], 16, %2;\n"
                 :: "r"(sa), "l"(g), "r"(sz));
}

// ---------------- GEMM: C[Mr,256] = A[Mr,256] @ W[256,256]^T + bias --------
// 2xTF32: A hi-only, W split hi/lo. Pure GEMM now (zero-fill moved to the
// attention launch). Block (0,0,0) also computes segment boundaries.
#define GP 36
#define SA_HI 0
#define SW_HI (128 * GP)
#define SW_LO (128 * GP + 64 * GP)
#define GEMM_SMEM_U32 (128 * GP + 2 * 64 * GP)

extern __shared__ unsigned sm_gemm[];

__global__ __launch_bounds__(256, 3)
void gemm3_tf32(const float* __restrict__ A0, const float* __restrict__ A12,
                const float* __restrict__ W0, const float* __restrict__ b0,
                const float* __restrict__ W1, const float* __restrict__ b1,
                const float* __restrict__ W2, const float* __restrict__ b2,
                float* __restrict__ C0, float* __restrict__ C1, float* __restrict__ C2,
                const int* __restrict__ qb, const int* __restrict__ kb,
                int nq, int mk) {
    int t = threadIdx.x;

    // segment boundaries (one block, runs before its GEMM work)
    if (qb != nullptr && blockIdx.x == 0 && blockIdx.y == 0 && blockIdx.z == 0
        && t <= NB) {
        int b = t;
        int lo = 0, hi = nq;
        while (lo < hi) { int mid = (lo + hi) >> 1; if (qb[mid] < b) lo = mid + 1; else hi = mid; }
        g_qseg[b] = lo;
        lo = 0; hi = mk;
        while (lo < hi) { int mid = (lo + hi) >> 1; if (kb[mid] < b) lo = mid + 1; else hi = mid; }
        g_kseg[b] = lo;
    }

    int z = blockIdx.z;
    const float* A    = (z == 0) ? A0 : A12;
    const float* W    = (z == 0) ? W0 : ((z == 1) ? W1 : W2);
    const float* bias = (z == 0) ? b0 : ((z == 1) ? b1 : b2);
    float*       C    = (z == 0) ? C0 : ((z == 1) ? C1 : C2);

    int w = t >> 5, lane = t & 31;
    int gid = lane >> 2, tig = lane & 3;
    int m0 = blockIdx.x * 128;
    int n0 = blockIdx.y * 64;
    int wm = (w >> 1) * 32;
    int wn = (w & 1) * 32;

    unsigned* sAhi = sm_gemm + SA_HI;
    unsigned* sWhi = sm_gemm + SW_HI;
    unsigned* sWlo = sm_gemm + SW_LO;

    float acc[2][4][4] = {};

    for (int kk = 0; kk < DIM; kk += 32) {
        __syncthreads();
        #pragma unroll
        for (int i = 0; i < 4; i++) {
            int f = t + i * 256;
            int r = f >> 3, c4 = f & 7;
            float4 av = *(const float4*)&A[(size_t)(m0 + r) * DIM + kk + c4 * 4];
            sAhi[r * GP + c4 * 4 + 0] = f2tf32(av.x);
            sAhi[r * GP + c4 * 4 + 1] = f2tf32(av.y);
            sAhi[r * GP + c4 * 4 + 2] = f2tf32(av.z);
            sAhi[r * GP + c4 * 4 + 3] = f2tf32(av.w);
        }
        #pragma unroll
        for (int i = 0; i < 2; i++) {
            int f = t + i * 256;
            int r = f >> 3, c4 = f & 7;
            float4 wv = *(const float4*)&W[(size_t)(n0 + r) * DIM + kk + c4 * 4];
            float vv[4] = {wv.x, wv.y, wv.z, wv.w};
            #pragma unroll
            for (int e = 0; e < 4; e++) {
                unsigned hb = f2tf32(vv[e]);
                float hf = __uint_as_float(hb);
                sWhi[r * GP + c4 * 4 + e] = hb;
                sWlo[r * GP + c4 * 4 + e] = f2tf32(vv[e] - hf);
            }
        }
        __syncthreads();

        #pragma unroll
        for (int ks = 0; ks < 32; ks += 8) {
            unsigned ah[2][4], bh[4][2], bl[4][2];
            #pragma unroll
            for (int i = 0; i < 2; i++) {
                int mr = wm + i * 16 + gid;
                int c  = ks + tig;
                ah[i][0] = sAhi[mr * GP + c];
                ah[i][1] = sAhi[(mr + 8) * GP + c];
                ah[i][2] = sAhi[mr * GP + c + 4];
                ah[i][3] = sAhi[(mr + 8) * GP + c + 4];
            }
            #pragma unroll
            for (int j = 0; j < 4; j++) {
                int nr = wn + j * 8 + gid;
                int c  = ks + tig;
                bh[j][0] = sWhi[nr * GP + c];
                bh[j][1] = sWhi[nr * GP + c + 4];
                bl[j][0] = sWlo[nr * GP + c];
                bl[j][1] = sWlo[nr * GP + c + 4];
            }
            #pragma unroll
            for (int i = 0; i < 2; i++)
                #pragma unroll
                for (int j = 0; j < 4; j++) {
                    mma_tf32(acc[i][j], ah[i], bh[j]);
                    mma_tf32(acc[i][j], ah[i], bl[j]);
                }
        }
    }

    #pragma unroll
    for (int i = 0; i < 2; i++) {
        #pragma unroll
        for (int j = 0; j < 4; j++) {
            int n = n0 + wn + j * 8 + tig * 2;
            float bb0 = __ldg(&bias[n]), bb1 = __ldg(&bias[n + 1]);
            int m = m0 + wm + i * 16 + gid;
            *(float2*)&C[(size_t)m * DIM + n] =
                make_float2(acc[i][j][0] + bb0, acc[i][j][1] + bb1);
            *(float2*)&C[(size_t)(m + 8) * DIM + n] =
                make_float2(acc[i][j][2] + bb0, acc[i][j][3] + bb1);
        }
    }
}

// ---------------- tensor-core block-diagonal attention + fused zero ---------
// grid = (NB, 33). y==0: zero-fill blocks (batch b zeroes its rows OUTSIDE
// [ks,ke) — race-free vs attn blocks which write every [ks,ke) entry).
// y>=1: attn blocks, 32 query rows each, 2xTF32 MMA, software-pipelined
// cp.async (K and V in separate groups; next-K prefetch under PV, next-V
// under next QK).
#define AP 260
#define VP 264
#define PP 36
#define ATTN_SMEM_F (32 * AP * 2 + 32 * VP + 32 * PP + 32)

extern __shared__ float sm_attn[];

__global__ __launch_bounds__(256)
void attn_mma(const float* __restrict__ Q, const float* __restrict__ K,
              const float* __restrict__ V, float* __restrict__ attn,
              float* __restrict__ O, int Mtot) {
    int b  = blockIdx.x;
    int qs = g_qseg[b], qe = g_qseg[b + 1];
    int ks = g_kseg[b], ke = g_kseg[b + 1];
    int t = threadIdx.x;

    if (blockIdx.y == 0) {
        // zero-fill: rows [qs,qe), cols [0,ks) U [ke,Mtot)
        int m4 = Mtot >> 2;
        float4 z4 = make_float4(0.f, 0.f, 0.f, 0.f);
        for (int r = qs; r < qe; r++) {
            float* row = attn + (size_t)r * Mtot;
            for (int c4 = t; c4 < m4; c4 += 256) {
                int c = c4 * 4;
                if (c + 4 <= ks || c >= ke) {
                    __stcs((float4*)row + c4, z4);
                } else if (c < ks || c + 4 > ke) {
                    #pragma unroll
                    for (int e = 0; e < 4; e++) {
                        int cc = c + e;
                        if (cc < ks || cc >= ke) __stcs(row + cc, 0.f);
                    }
                }
            }
        }
        return;
    }

    int row0 = qs + ((int)blockIdx.y - 1) * 32;
    if (row0 >= qe) return;
    int rows = min(32, qe - row0);
    int nk = ke - ks;

    int w = t >> 5, lane = t & 31;
    int gid = lane >> 2, tig = lane & 3;

    float* Qs = sm_attn;
    float* Ks = Qs + 32 * AP;
    float* Vs = Ks + 32 * AP;
    float* Ps = Vs + 32 * VP;
    float* rowsum = Ps + 32 * PP;

    if (nk == 0) {
        for (int i = t; i < rows * DIM; i += 256)
            O[(size_t)row0 * DIM + i] = 0.f;
        return;
    }

    int ntiles = (nk + 31) >> 5;

    // prologue: Q group, K0 group, V0 group; wait for Q+K0 (V0 in flight)
    for (int i = t; i < 32 * 64; i += 256) {
        int r = i >> 6, c4 = i & 63;
        cp16z(&Qs[r * AP + c4 * 4], &Q[(size_t)(row0 + r) * DIM + c4 * 4], r < rows);
    }
    asm volatile("cp.async.commit_group;\n");
    for (int i = t; i < 32 * 64; i += 256) {
        int r = i >> 6, c4 = i & 63;
        cp16z(&Ks[r * AP + c4 * 4], &K[(size_t)(ks + r) * DIM + c4 * 4], r < nk);
    }
    asm volatile("cp.async.commit_group;\n");
    for (int i = t; i < 32 * 64; i += 256) {
        int r = i >> 6, c4 = i & 63;
        cp16z(&Vs[r * VP + c4 * 4], &V[(size_t)(ks + r) * DIM + c4 * 4], r < nk);
    }
    asm volatile("cp.async.commit_group;\n");
    asm volatile("cp.async.wait_group 1;\n" ::: "memory");
    if (t < 32) rowsum[t] = 0.f;

    int mh  = w & 1;
    int wn0 = (w >> 1) * 8;

    float o_acc[2][4][4] = {};

    for (int kt = 0; kt < ntiles; kt++) {
        int kbase = kt << 5;
        bool more = (kt + 1 < ntiles);
        if (kt > 0)
            asm volatile("cp.async.wait_group 1;\n" ::: "memory");  // K[kt] done
        __syncthreads();                 // K[kt] (and Q) visible to all

        // ---- QK^T, 2-pass: Q hi-only, K split ----
        float sacc[4] = {0.f, 0.f, 0.f, 0.f};
        #pragma unroll
        for (int kk = 0; kk < DIM; kk += 8) {
            unsigned ah[4], bh[2], bl[2];
            int c = kk + tig;
            int mr = mh * 16 + gid;
            ah[0] = f2tf32(Qs[mr * AP + c]);
            ah[1] = f2tf32(Qs[(mr + 8) * AP + c]);
            ah[2] = f2tf32(Qs[mr * AP + c + 4]);
            ah[3] = f2tf32(Qs[(mr + 8) * AP + c + 4]);
            int nr = wn0 + gid;
            split_tf32(Ks[nr * AP + c],     bh[0], bl[0]);
            split_tf32(Ks[nr * AP + c + 4], bh[1], bl[1]);
            mma_tf32(sacc, ah, bh);
            mma_tf32(sacc, ah, bl);
        }
        int kn = kbase + wn0 + 2 * tig;
        float e0 = (kn     < nk) ? __expf(sacc[0] * SCALE) : 0.f;
        float e1 = (kn + 1 < nk) ? __expf(sacc[1] * SCALE) : 0.f;
        float e2 = (kn     < nk) ? __expf(sacc[2] * SCALE) : 0.f;
        float e3 = (kn + 1 < nk) ? __expf(sacc[3] * SCALE) : 0.f;
        int pr = mh * 16 + gid;
        Ps[pr * PP + wn0 + 2 * tig]           = e0;
        Ps[pr * PP + wn0 + 2 * tig + 1]       = e1;
        Ps[(pr + 8) * PP + wn0 + 2 * tig]     = e2;
        Ps[(pr + 8) * PP + wn0 + 2 * tig + 1] = e3;
        __syncthreads();                 // P visible; all Ks reads done

        // prefetch K[kt+1] into Ks (hides under rowsum+PV)
        if (more) {
            int kb2 = kbase + 32;
            for (int i = t; i < 32 * 64; i += 256) {
                int r = i >> 6, c4 = i & 63;
                cp16z(&Ks[r * AP + c4 * 4],
                      &K[(size_t)(ks + kb2 + r) * DIM + c4 * 4], kb2 + r < nk);
            }
            asm volatile("cp.async.commit_group;\n");
        }

        // ---- unnormalized attn write + rowsum ----
        #pragma unroll
        for (int i = 0; i < 4; i++) {
            int r = w + i * 8;
            float e = Ps[r * PP + lane];
            float s = e;
            #pragma unroll
            for (int off = 16; off; off >>= 1) s += __shfl_xor_sync(0xFFFFFFFFu, s, off);
            if (lane == 0) rowsum[r] += s;
            if (r < rows && kbase + lane < nk)
                attn[(size_t)(row0 + r) * Mtot + ks + kbase + lane] = e;
        }

        // V[kt] must be complete before PV
        if (more) asm volatile("cp.async.wait_group 1;\n" ::: "memory");
        else      asm volatile("cp.async.wait_group 0;\n" ::: "memory");
        __syncthreads();                 // V[kt] visible to all

        // ---- PV, 2-pass: P hi-only, V split ----
        #pragma unroll
        for (int kk = 0; kk < 32; kk += 8) {
            unsigned pah[2][4];
            int c = kk + tig;
            #pragma unroll
            for (int i = 0; i < 2; i++) {
                int mr = i * 16 + gid;
                pah[i][0] = f2tf32(Ps[mr * PP + c]);
                pah[i][1] = f2tf32(Ps[(mr + 8) * PP + c]);
                pah[i][2] = f2tf32(Ps[mr * PP + c + 4]);
                pah[i][3] = f2tf32(Ps[(mr + 8) * PP + c + 4]);
            }
            #pragma unroll
            for (int j = 0; j < 4; j++) {
                int n = w * 32 + 8 * j + gid;
                unsigned vbh[2], vbl[2];
                split_tf32(Vs[c * VP + n],       vbh[0], vbl[0]);
                split_tf32(Vs[(c + 4) * VP + n], vbh[1], vbl[1]);
                #pragma unroll
                for (int i = 0; i < 2; i++) {
                    mma_tf32(o_acc[i][j], pah[i], vbh);
                    mma_tf32(o_acc[i][j], pah[i], vbl);
                }
            }
        }
        __syncthreads();                 // all Vs reads done

        // prefetch V[kt+1] into Vs (hides under next QK)
        if (more) {
            int kb2 = kbase + 32;
            for (int i = t; i < 32 * 64; i += 256) {
                int r = i >> 6, c4 = i & 63;
                cp16z(&Vs[r * VP + c4 * 4],
                      &V[(size_t)(ks + kb2 + r) * DIM + c4 * 4], kb2 + r < nk);
            }
            asm volatile("cp.async.commit_group;\n");
        }
    }
    __syncthreads();
    if (t < 32) rowsum[t] = (rowsum[t] > 0.f) ? (1.f / rowsum[t]) : 0.f;
    __syncthreads();

    // normalize attn in place (warp-per-row, coalesced)
    #pragma unroll
    for (int i = 0; i < 4; i++) {
        int r = w + i * 8;
        if (r < rows) {
            float inv = rowsum[r];
            size_t base = (size_t)(row0 + r) * Mtot + ks;
            for (int j = lane; j < nk; j += 32) attn[base + j] *= inv;
        }
    }
    #pragma unroll
    for (int i = 0; i < 2; i++) {
        int r = i * 16 + gid;
        if (r < rows) {
            float inv = rowsum[r];
            #pragma unroll
            for (int j = 0; j < 4; j++) {
                int n = w * 32 + 8 * j + 2 * tig;
                *(float2*)&O[(size_t)(row0 + r) * DIM + n] =
                    make_float2(o_acc[i][j][0] * inv, o_acc[i][j][1] * inv);
            }
        }
        int r8 = r + 8;
        if (r8 < rows) {
            float inv = rowsum[r8];
            #pragma unroll
            for (int j = 0; j < 4; j++) {
                int n = w * 32 + 8 * j + 2 * tig;
                *(float2*)&O[(size_t)(row0 + r8) * DIM + n] =
                    make_float2(o_acc[i][j][2] * inv, o_acc[i][j][3] * inv);
            }
        }
    }
}

// ---------------- launch (single stream, no events) -------------------------
extern "C" void kernel_launch(void* const* d_in, const int* in_sizes, int n_in,
                              void* d_out, int out_size) {
    const float* q_feat = (const float*)d_in[0];
    const float* k_feat = (const float*)d_in[1];
    const int*   q_batch = (const int*)d_in[2];
    const int*   k_batch = (const int*)d_in[3];
    const float* Wq = (const float*)d_in[4];
    const float* bq = (const float*)d_in[5];
    const float* Wk = (const float*)d_in[6];
    const float* bk = (const float*)d_in[7];
    const float* Wv = (const float*)d_in[8];
    const float* bv = (const float*)d_in[9];
    const float* Wo = (const float*)d_in[10];
    const float* bo = (const float*)d_in[11];

    int n = in_sizes[0] / DIM;
    int m = in_sizes[1] / DIM;

    float* out      = (float*)d_out;
    float* attended = out;                        // [n, DIM]
    float* attn     = out + (size_t)n * DIM;      // [n, m]

    float *Qd, *Kd, *Vd, *Od;
    cudaGetSymbolAddress((void**)&Qd, g_Q);
    cudaGetSymbolAddress((void**)&Kd, g_K);
    cudaGetSymbolAddress((void**)&Vd, g_V);
    cudaGetSymbolAddress((void**)&Od, g_O);

    const size_t attn_smem = ATTN_SMEM_F * sizeof(float);
    const size_t gemm_smem = GEMM_SMEM_U32 * sizeof(unsigned);
    cudaFuncSetAttribute(attn_mma, cudaFuncAttributeMaxDynamicSharedMemorySize,
                         (int)attn_smem);
    cudaFuncSetAttribute(gemm3_tf32, cudaFuncAttributeMaxDynamicSharedMemorySize,
                         (int)gemm_smem);

    // 1. fused QKV projection (pure GEMM) + segment boundaries
    gemm3_tf32<<<dim3(n / 128, 4, 3), 256, gemm_smem>>>(
        q_feat, k_feat, Wq, bq, Wk, bk, Wv, bv, Qd, Kd, Vd,
        q_batch, k_batch, n, m);
    // 2. attention + fused zero-fill (y==0 zero blocks dispatch first)
    attn_mma<<<dim3(NB, 33), 256, attn_smem>>>(Qd, Kd, Vd, attn, Od, m);
    // 3. output projection
    gemm3_tf32<<<dim3(n / 128, 4, 1), 256, gemm_smem>>>(
        Od, Od, Wo, bo, Wo, bo, Wo, bo, attended, attended, attended,
        nullptr, nullptr, 0, 0);
}

// round 13
// speedup vs baseline: 1.1413x; 1.1413x over previous
#include <cuda_runtime.h>
#include <cstdint>

#define NQMAX 8192
#define DIM   256
#define NB    64
#define SCALE 0.0625f   /* 1/sqrt(256) exactly */
#define NZY   4         /* zero blocks per batch in the attn launch */

// ---------------- scratch (device globals: allocation-free) ----------------
__device__ float g_Q[NQMAX * DIM];
__device__ float g_K[NQMAX * DIM];
__device__ float g_V[NQMAX * DIM];
__device__ float g_O[NQMAX * DIM];
__device__ int   g_qseg[NB + 1];
__device__ int   g_kseg[NB + 1];

// ---------------- tf32 / mma helpers ---------------------------------------
__device__ __forceinline__ unsigned f2tf32(float x) {
    unsigned r;
    asm("cvt.rna.tf32.f32 %0, %1;" : "=r"(r) : "f"(x));
    return r;
}
__device__ __forceinline__ void split_tf32(float x, unsigned& hi, unsigned& lo) {
    hi = f2tf32(x);
    lo = f2tf32(x - __uint_as_float(hi));
}
__device__ __forceinline__ void mma_tf32(float* d, const unsigned* a, const unsigned* b) {
    asm volatile(
        "mma.sync.aligned.m16n8k8.row.col.f32.tf32.tf32.f32 "
        "{%0,%1,%2,%3}, {%4,%5,%6,%7}, {%8,%9}, {%0,%1,%2,%3};\n"
        : "+f"(d[0]), "+f"(d[1]), "+f"(d[2]), "+f"(d[3])
        : "r"(a[0]), "r"(a[1]), "r"(a[2]), "r"(a[3]), "r"(b[0]), "r"(b[1]));
}
__device__ __forceinline__ void cp16z(void* s, const void* g, bool p) {
    unsigned sa = (unsigned)__cvta_generic_to_shared(s);
    int sz = p ? 16 : 0;
    asm volatile("cp.async.cg.shared.global [%0], [%1], 16, %2;\n"
                 :: "r"(sa), "l"(g), "r"(sz));
}

// ---------------- GEMM: C[Mr,256] = A[Mr,256] @ W[256,256]^T + bias --------
// 2xTF32: A hi-only, W split hi/lo. Pure GEMM (measured 54.6us for QKV).
// Block (0,0,0) also computes segment boundaries.
#define GP 36
#define SA_HI 0
#define SW_HI (128 * GP)
#define SW_LO (128 * GP + 64 * GP)
#define GEMM_SMEM_U32 (128 * GP + 2 * 64 * GP)

extern __shared__ unsigned sm_gemm[];

__global__ __launch_bounds__(256, 3)
void gemm3_tf32(const float* __restrict__ A0, const float* __restrict__ A12,
                const float* __restrict__ W0, const float* __restrict__ b0,
                const float* __restrict__ W1, const float* __restrict__ b1,
                const float* __restrict__ W2, const float* __restrict__ b2,
                float* __restrict__ C0, float* __restrict__ C1, float* __restrict__ C2,
                const int* __restrict__ qb, const int* __restrict__ kb,
                int nq, int mk) {
    int t = threadIdx.x;

    // segment boundaries (one block, runs before its GEMM work)
    if (qb != nullptr && blockIdx.x == 0 && blockIdx.y == 0 && blockIdx.z == 0
        && t <= NB) {
        int b = t;
        int lo = 0, hi = nq;
        while (lo < hi) { int mid = (lo + hi) >> 1; if (qb[mid] < b) lo = mid + 1; else hi = mid; }
        g_qseg[b] = lo;
        lo = 0; hi = mk;
        while (lo < hi) { int mid = (lo + hi) >> 1; if (kb[mid] < b) lo = mid + 1; else hi = mid; }
        g_kseg[b] = lo;
    }

    int z = blockIdx.z;
    const float* A    = (z == 0) ? A0 : A12;
    const float* W    = (z == 0) ? W0 : ((z == 1) ? W1 : W2);
    const float* bias = (z == 0) ? b0 : ((z == 1) ? b1 : b2);
    float*       C    = (z == 0) ? C0 : ((z == 1) ? C1 : C2);

    int w = t >> 5, lane = t & 31;
    int gid = lane >> 2, tig = lane & 3;
    int m0 = blockIdx.x * 128;
    int n0 = blockIdx.y * 64;
    int wm = (w >> 1) * 32;
    int wn = (w & 1) * 32;

    unsigned* sAhi = sm_gemm + SA_HI;
    unsigned* sWhi = sm_gemm + SW_HI;
    unsigned* sWlo = sm_gemm + SW_LO;

    float acc[2][4][4] = {};

    for (int kk = 0; kk < DIM; kk += 32) {
        __syncthreads();
        #pragma unroll
        for (int i = 0; i < 4; i++) {
            int f = t + i * 256;
            int r = f >> 3, c4 = f & 7;
            float4 av = *(const float4*)&A[(size_t)(m0 + r) * DIM + kk + c4 * 4];
            sAhi[r * GP + c4 * 4 + 0] = f2tf32(av.x);
            sAhi[r * GP + c4 * 4 + 1] = f2tf32(av.y);
            sAhi[r * GP + c4 * 4 + 2] = f2tf32(av.z);
            sAhi[r * GP + c4 * 4 + 3] = f2tf32(av.w);
        }
        #pragma unroll
        for (int i = 0; i < 2; i++) {
            int f = t + i * 256;
            int r = f >> 3, c4 = f & 7;
            float4 wv = *(const float4*)&W[(size_t)(n0 + r) * DIM + kk + c4 * 4];
            float vv[4] = {wv.x, wv.y, wv.z, wv.w};
            #pragma unroll
            for (int e = 0; e < 4; e++) {
                unsigned hb = f2tf32(vv[e]);
                float hf = __uint_as_float(hb);
                sWhi[r * GP + c4 * 4 + e] = hb;
                sWlo[r * GP + c4 * 4 + e] = f2tf32(vv[e] - hf);
            }
        }
        __syncthreads();

        #pragma unroll
        for (int ks = 0; ks < 32; ks += 8) {
            unsigned ah[2][4], bh[4][2], bl[4][2];
            #pragma unroll
            for (int i = 0; i < 2; i++) {
                int mr = wm + i * 16 + gid;
                int c  = ks + tig;
                ah[i][0] = sAhi[mr * GP + c];
                ah[i][1] = sAhi[(mr + 8) * GP + c];
                ah[i][2] = sAhi[mr * GP + c + 4];
                ah[i][3] = sAhi[(mr + 8) * GP + c + 4];
            }
            #pragma unroll
            for (int j = 0; j < 4; j++) {
                int nr = wn + j * 8 + gid;
                int c  = ks + tig;
                bh[j][0] = sWhi[nr * GP + c];
                bh[j][1] = sWhi[nr * GP + c + 4];
                bl[j][0] = sWlo[nr * GP + c];
                bl[j][1] = sWlo[nr * GP + c + 4];
            }
            #pragma unroll
            for (int i = 0; i < 2; i++)
                #pragma unroll
                for (int j = 0; j < 4; j++) {
                    mma_tf32(acc[i][j], ah[i], bh[j]);
                    mma_tf32(acc[i][j], ah[i], bl[j]);
                }
        }
    }

    #pragma unroll
    for (int i = 0; i < 2; i++) {
        #pragma unroll
        for (int j = 0; j < 4; j++) {
            int n = n0 + wn + j * 8 + tig * 2;
            float bb0 = __ldg(&bias[n]), bb1 = __ldg(&bias[n + 1]);
            int m = m0 + wm + i * 16 + gid;
            *(float2*)&C[(size_t)m * DIM + n] =
                make_float2(acc[i][j][0] + bb0, acc[i][j][1] + bb1);
            *(float2*)&C[(size_t)(m + 8) * DIM + n] =
                make_float2(acc[i][j][2] + bb0, acc[i][j][3] + bb1);
        }
    }
}

// ---------------- tensor-core block-diagonal attention + fused zero ---------
// grid = (NB, 32 + NZY). y < NZY: zero-fill blocks (4 per batch, dispatched
// first; block y zeroes rows qs+y, qs+y+NZY, ... outside [ks,ke) — race-free
// vs attn blocks which write every [ks,ke) entry). y >= NZY: attn blocks,
// 32 query rows each, 2xTF32 MMA, software-pipelined cp.async.
#define AP 260
#define VP 264
#define PP 36
#define ATTN_SMEM_F (32 * AP * 2 + 32 * VP + 32 * PP + 32)

extern __shared__ float sm_attn[];

__global__ __launch_bounds__(256)
void attn_mma(const float* __restrict__ Q, const float* __restrict__ K,
              const float* __restrict__ V, float* __restrict__ attn,
              float* __restrict__ O, int Mtot) {
    int b  = blockIdx.x;
    int qs = g_qseg[b], qe = g_qseg[b + 1];
    int ks = g_kseg[b], ke = g_kseg[b + 1];
    int t = threadIdx.x;

    if (blockIdx.y < NZY) {
        // zero-fill: rows qs+y, qs+y+NZY, ...; cols [0,ks) U [ke,Mtot)
        int m4 = Mtot >> 2;
        float4 z4 = make_float4(0.f, 0.f, 0.f, 0.f);
        for (int r = qs + (int)blockIdx.y; r < qe; r += NZY) {
            float* row = attn + (size_t)r * Mtot;
            for (int c4 = t; c4 < m4; c4 += 256) {
                int c = c4 * 4;
                if (c + 4 <= ks || c >= ke) {
                    __stcs((float4*)row + c4, z4);
                } else if (c < ks || c + 4 > ke) {
                    #pragma unroll
                    for (int e = 0; e < 4; e++) {
                        int cc = c + e;
                        if (cc < ks || cc >= ke) __stcs(row + cc, 0.f);
                    }
                }
            }
        }
        return;
    }

    int row0 = qs + ((int)blockIdx.y - NZY) * 32;
    if (row0 >= qe) return;
    int rows = min(32, qe - row0);
    int nk = ke - ks;

    int w = t >> 5, lane = t & 31;
    int gid = lane >> 2, tig = lane & 3;

    float* Qs = sm_attn;
    float* Ks = Qs + 32 * AP;
    float* Vs = Ks + 32 * AP;
    float* Ps = Vs + 32 * VP;
    float* rowsum = Ps + 32 * PP;

    if (nk == 0) {
        for (int i = t; i < rows * DIM; i += 256)
            O[(size_t)row0 * DIM + i] = 0.f;
        return;
    }

    int ntiles = (nk + 31) >> 5;

    // prologue: Q group, K0 group, V0 group; wait for Q+K0 (V0 in flight)
    for (int i = t; i < 32 * 64; i += 256) {
        int r = i >> 6, c4 = i & 63;
        cp16z(&Qs[r * AP + c4 * 4], &Q[(size_t)(row0 + r) * DIM + c4 * 4], r < rows);
    }
    asm volatile("cp.async.commit_group;\n");
    for (int i = t; i < 32 * 64; i += 256) {
        int r = i >> 6, c4 = i & 63;
        cp16z(&Ks[r * AP + c4 * 4], &K[(size_t)(ks + r) * DIM + c4 * 4], r < nk);
    }
    asm volatile("cp.async.commit_group;\n");
    for (int i = t; i < 32 * 64; i += 256) {
        int r = i >> 6, c4 = i & 63;
        cp16z(&Vs[r * VP + c4 * 4], &V[(size_t)(ks + r) * DIM + c4 * 4], r < nk);
    }
    asm volatile("cp.async.commit_group;\n");
    asm volatile("cp.async.wait_group 1;\n" ::: "memory");
    if (t < 32) rowsum[t] = 0.f;

    int mh  = w & 1;
    int wn0 = (w >> 1) * 8;

    float o_acc[2][4][4] = {};

    for (int kt = 0; kt < ntiles; kt++) {
        int kbase = kt << 5;
        bool more = (kt + 1 < ntiles);
        if (kt > 0)
            asm volatile("cp.async.wait_group 1;\n" ::: "memory");  // K[kt] done
        __syncthreads();                 // K[kt] (and Q) visible to all

        // ---- QK^T, 2-pass: Q hi-only, K split ----
        float sacc[4] = {0.f, 0.f, 0.f, 0.f};
        #pragma unroll
        for (int kk = 0; kk < DIM; kk += 8) {
            unsigned ah[4], bh[2], bl[2];
            int c = kk + tig;
            int mr = mh * 16 + gid;
            ah[0] = f2tf32(Qs[mr * AP + c]);
            ah[1] = f2tf32(Qs[(mr + 8) * AP + c]);
            ah[2] = f2tf32(Qs[mr * AP + c + 4]);
            ah[3] = f2tf32(Qs[(mr + 8) * AP + c + 4]);
            int nr = wn0 + gid;
            split_tf32(Ks[nr * AP + c],     bh[0], bl[0]);
            split_tf32(Ks[nr * AP + c + 4], bh[1], bl[1]);
            mma_tf32(sacc, ah, bh);
            mma_tf32(sacc, ah, bl);
        }
        int kn = kbase + wn0 + 2 * tig;
        float e0 = (kn     < nk) ? __expf(sacc[0] * SCALE) : 0.f;
        float e1 = (kn + 1 < nk) ? __expf(sacc[1] * SCALE) : 0.f;
        float e2 = (kn     < nk) ? __expf(sacc[2] * SCALE) : 0.f;
        float e3 = (kn + 1 < nk) ? __expf(sacc[3] * SCALE) : 0.f;
        int pr = mh * 16 + gid;
        Ps[pr * PP + wn0 + 2 * tig]           = e0;
        Ps[pr * PP + wn0 + 2 * tig + 1]       = e1;
        Ps[(pr + 8) * PP + wn0 + 2 * tig]     = e2;
        Ps[(pr + 8) * PP + wn0 + 2 * tig + 1] = e3;
        __syncthreads();                 // P visible; all Ks reads done

        // prefetch K[kt+1] into Ks (hides under rowsum+PV)
        if (more) {
            int kb2 = kbase + 32;
            for (int i = t; i < 32 * 64; i += 256) {
                int r = i >> 6, c4 = i & 63;
                cp16z(&Ks[r * AP + c4 * 4],
                      &K[(size_t)(ks + kb2 + r) * DIM + c4 * 4], kb2 + r < nk);
            }
            asm volatile("cp.async.commit_group;\n");
        }

        // ---- unnormalized attn write + rowsum ----
        #pragma unroll
        for (int i = 0; i < 4; i++) {
            int r = w + i * 8;
            float e = Ps[r * PP + lane];
            float s = e;
            #pragma unroll
            for (int off = 16; off; off >>= 1) s += __shfl_xor_sync(0xFFFFFFFFu, s, off);
            if (lane == 0) rowsum[r] += s;
            if (r < rows && kbase + lane < nk)
                attn[(size_t)(row0 + r) * Mtot + ks + kbase + lane] = e;
        }

        // V[kt] must be complete before PV
        if (more) asm volatile("cp.async.wait_group 1;\n" ::: "memory");
        else      asm volatile("cp.async.wait_group 0;\n" ::: "memory");
        __syncthreads();                 // V[kt] visible to all

        // ---- PV, 2-pass: P hi-only, V split ----
        #pragma unroll
        for (int kk = 0; kk < 32; kk += 8) {
            unsigned pah[2][4];
            int c = kk + tig;
            #pragma unroll
            for (int i = 0; i < 2; i++) {
                int mr = i * 16 + gid;
                pah[i][0] = f2tf32(Ps[mr * PP + c]);
                pah[i][1] = f2tf32(Ps[(mr + 8) * PP + c]);
                pah[i][2] = f2tf32(Ps[mr * PP + c + 4]);
                pah[i][3] = f2tf32(Ps[(mr + 8) * PP + c + 4]);
            }
            #pragma unroll
            for (int j = 0; j < 4; j++) {
                int n = w * 32 + 8 * j + gid;
                unsigned vbh[2], vbl[2];
                split_tf32(Vs[c * VP + n],       vbh[0], vbl[0]);
                split_tf32(Vs[(c + 4) * VP + n], vbh[1], vbl[1]);
                #pragma unroll
                for (int i = 0; i < 2; i++) {
                    mma_tf32(o_acc[i][j], pah[i], vbh);
                    mma_tf32(o_acc[i][j], pah[i], vbl);
                }
            }
        }
        __syncthreads();                 // all Vs reads done

        // prefetch V[kt+1] into Vs (hides under next QK)
        if (more) {
            int kb2 = kbase + 32;
            for (int i = t; i < 32 * 64; i += 256) {
                int r = i >> 6, c4 = i & 63;
                cp16z(&Vs[r * VP + c4 * 4],
                      &V[(size_t)(ks + kb2 + r) * DIM + c4 * 4], kb2 + r < nk);
            }
            asm volatile("cp.async.commit_group;\n");
        }
    }
    __syncthreads();
    if (t < 32) rowsum[t] = (rowsum[t] > 0.f) ? (1.f / rowsum[t]) : 0.f;
    __syncthreads();

    // normalize attn in place (warp-per-row, coalesced)
    #pragma unroll
    for (int i = 0; i < 4; i++) {
        int r = w + i * 8;
        if (r < rows) {
            float inv = rowsum[r];
            size_t base = (size_t)(row0 + r) * Mtot + ks;
            for (int j = lane; j < nk; j += 32) attn[base + j] *= inv;
        }
    }
    #pragma unroll
    for (int i = 0; i < 2; i++) {
        int r = i * 16 + gid;
        if (r < rows) {
            float inv = rowsum[r];
            #pragma unroll
            for (int j = 0; j < 4; j++) {
                int n = w * 32 + 8 * j + 2 * tig;
                *(float2*)&O[(size_t)(row0 + r) * DIM + n] =
                    make_float2(o_acc[i][j][0] * inv, o_acc[i][j][1] * inv);
            }
        }
        int r8 = r + 8;
        if (r8 < rows) {
            float inv = rowsum[r8];
            #pragma unroll
            for (int j = 0; j < 4; j++) {
                int n = w * 32 + 8 * j + 2 * tig;
                *(float2*)&O[(size_t)(row0 + r8) * DIM + n] =
                    make_float2(o_acc[i][j][2] * inv, o_acc[i][j][3] * inv);
            }
        }
    }
}

// ---------------- launch (single stream, no events) -------------------------
extern "C" void kernel_launch(void* const* d_in, const int* in_sizes, int n_in,
                              void* d_out, int out_size) {
    const float* q_feat = (const float*)d_in[0];
    const float* k_feat = (const float*)d_in[1];
    const int*   q_batch = (const int*)d_in[2];
    const int*   k_batch = (const int*)d_in[3];
    const float* Wq = (const float*)d_in[4];
    const float* bq = (const float*)d_in[5];
    const float* Wk = (const float*)d_in[6];
    const float* bk = (const float*)d_in[7];
    const float* Wv = (const float*)d_in[8];
    const float* bv = (const float*)d_in[9];
    const float* Wo = (const float*)d_in[10];
    const float* bo = (const float*)d_in[11];

    int n = in_sizes[0] / DIM;
    int m = in_sizes[1] / DIM;

    float* out      = (float*)d_out;
    float* attended = out;                        // [n, DIM]
    float* attn     = out + (size_t)n * DIM;      // [n, m]

    float *Qd, *Kd, *Vd, *Od;
    cudaGetSymbolAddress((void**)&Qd, g_Q);
    cudaGetSymbolAddress((void**)&Kd, g_K);
    cudaGetSymbolAddress((void**)&Vd, g_V);
    cudaGetSymbolAddress((void**)&Od, g_O);

    const size_t attn_smem = ATTN_SMEM_F * sizeof(float);
    const size_t gemm_smem = GEMM_SMEM_U32 * sizeof(unsigned);
    cudaFuncSetAttribute(attn_mma, cudaFuncAttributeMaxDynamicSharedMemorySize,
                         (int)attn_smem);
    cudaFuncSetAttribute(gemm3_tf32, cudaFuncAttributeMaxDynamicSharedMemorySize,
                         (int)gemm_smem);

    // 1. fused QKV projection (pure GEMM) + segment boundaries
    gemm3_tf32<<<dim3(n / 128, 4, 3), 256, gemm_smem>>>(
        q_feat, k_feat, Wq, bq, Wk, bk, Wv, bv, Qd, Kd, Vd,
        q_batch, k_batch, n, m);
    // 2. attention + fused zero-fill (256 zero blocks dispatch first)
    attn_mma<<<dim3(NB, 32 + NZY), 256, attn_smem>>>(Qd, Kd, Vd, attn, Od, m);
    // 3. output projection
    gemm3_tf32<<<dim3(n / 128, 4, 1), 256, gemm_smem>>>(
        Od, Od, Wo, bo, Wo, bo, Wo, bo, attended, attended, attended,
        nullptr, nullptr, 0, 0);
}

// round 15
// speedup vs baseline: 1.2055x; 1.0563x over previous
#include <cuda_runtime.h>
#include <cstdint>

#define NQMAX 8192
#define DIM   256
#define NB    64
#define SCALE 0.0625f   /* 1/sqrt(256) exactly */
#define NZY   8         /* zero blocks per batch in the attn launch */

// ---------------- scratch (device globals: allocation-free) ----------------
__device__ float g_Q[NQMAX * DIM];
__device__ float g_K[NQMAX * DIM];
__device__ float g_V[NQMAX * DIM];
__device__ float g_O[NQMAX * DIM];
__device__ int   g_qseg[NB + 1];
__device__ int   g_kseg[NB + 1];

// ---------------- tf32 / bf16 / mma helpers --------------------------------
__device__ __forceinline__ unsigned f2tf32(float x) {
    unsigned r;
    asm("cvt.rna.tf32.f32 %0, %1;" : "=r"(r) : "f"(x));
    return r;
}
__device__ __forceinline__ void split_tf32(float x, unsigned& hi, unsigned& lo) {
    hi = f2tf32(x);
    lo = f2tf32(x - __uint_as_float(hi));
}
// pack {lo-half = bf16(x), hi-half = bf16(y)}  (PTX: first source -> high)
__device__ __forceinline__ unsigned pack_bf16x2(float x, float y) {
    unsigned r;
    asm("cvt.rn.bf16x2.f32 %0, %1, %2;" : "=r"(r) : "f"(y), "f"(x));
    return r;
}
// tf32 mma m16n8k8 (attn path)
__device__ __forceinline__ void mma_tf32(float* d, const unsigned* a, const unsigned* b) {
    asm volatile(
        "mma.sync.aligned.m16n8k8.row.col.f32.tf32.tf32.f32 "
        "{%0,%1,%2,%3}, {%4,%5,%6,%7}, {%8,%9}, {%0,%1,%2,%3};\n"
        : "+f"(d[0]), "+f"(d[1]), "+f"(d[2]), "+f"(d[3])
        : "r"(a[0]), "r"(a[1]), "r"(a[2]), "r"(a[3]), "r"(b[0]), "r"(b[1]));
}
// bf16 mma m16n8k16 (GEMM path) — same register shape, 2x work per instr
__device__ __forceinline__ void mma_bf16(float* d, const unsigned* a, const unsigned* b) {
    asm volatile(
        "mma.sync.aligned.m16n8k16.row.col.f32.bf16.bf16.f32 "
        "{%0,%1,%2,%3}, {%4,%5,%6,%7}, {%8,%9}, {%0,%1,%2,%3};\n"
        : "+f"(d[0]), "+f"(d[1]), "+f"(d[2]), "+f"(d[3])
        : "r"(a[0]), "r"(a[1]), "r"(a[2]), "r"(a[3]), "r"(b[0]), "r"(b[1]));
}
__device__ __forceinline__ void cp16z(void* s, const void* g, bool p) {
    unsigned sa = (unsigned)__cvta_generic_to_shared(s);
    int sz = p ? 16 : 0;
    asm volatile("cp.async.cg.shared.global [%0], [%1], 16, %2;\n"
                 :: "r"(sa), "l"(g), "r"(sz));
}
// split a float4 into bf16x2 hi-words and lo-residual words (k-pairs)
__device__ __forceinline__ void split4_bf16(float4 v, unsigned& h0, unsigned& h1,
                                            unsigned& l0, unsigned& l1) {
    h0 = pack_bf16x2(v.x, v.y);
    h1 = pack_bf16x2(v.z, v.w);
    float hx = __uint_as_float(h0 << 16);
    float hy = __uint_as_float(h0 & 0xffff0000u);
    float hz = __uint_as_float(h1 << 16);
    float hw = __uint_as_float(h1 & 0xffff0000u);
    l0 = pack_bf16x2(v.x - hx, v.y - hy);
    l1 = pack_bf16x2(v.z - hz, v.w - hw);
}

// ---------------- GEMM: C[Mr,256] = A[Mr,256] @ W[256,256]^T + bias --------
// 3-pass bf16 (hi*hi + hi*lo + lo*hi) on m16n8k16: dropped lo*lo ~4e-6 rel.
// k=32 chunk = 2 k-steps (was 4 with tf32 k8): 64 LDS + 48 MMA per chunk
// (was 96 + 64). smem pitch 20 u32 (bf16 pairs): per-instruction banks
// (20*gid + tig) mod 32 = permutation -> conflict-free.
#define GPB 20
#define SA_HI 0
#define SA_LO (128 * GPB)
#define SW_HI (2 * 128 * GPB)
#define SW_LO (2 * 128 * GPB + 64 * GPB)
#define GEMM_SMEM_U32 (2 * 128 * GPB + 2 * 64 * GPB)   /* 30720 bytes */

extern __shared__ unsigned sm_gemm[];

__global__ __launch_bounds__(256, 3)
void gemm3_bf16(const float* __restrict__ A0, const float* __restrict__ A12,
                const float* __restrict__ W0, const float* __restrict__ b0,
                const float* __restrict__ W1, const float* __restrict__ b1,
                const float* __restrict__ W2, const float* __restrict__ b2,
                float* __restrict__ C0, float* __restrict__ C1, float* __restrict__ C2,
                const int* __restrict__ qb, const int* __restrict__ kb,
                int nq, int mk) {
    int t = threadIdx.x;

    // segment boundaries (one block, runs before its GEMM work)
    if (qb != nullptr && blockIdx.x == 0 && blockIdx.y == 0 && blockIdx.z == 0
        && t <= NB) {
        int b = t;
        int lo = 0, hi = nq;
        while (lo < hi) { int mid = (lo + hi) >> 1; if (qb[mid] < b) lo = mid + 1; else hi = mid; }
        g_qseg[b] = lo;
        lo = 0; hi = mk;
        while (lo < hi) { int mid = (lo + hi) >> 1; if (kb[mid] < b) lo = mid + 1; else hi = mid; }
        g_kseg[b] = lo;
    }

    int z = blockIdx.z;
    const float* A    = (z == 0) ? A0 : A12;
    const float* W    = (z == 0) ? W0 : ((z == 1) ? W1 : W2);
    const float* bias = (z == 0) ? b0 : ((z == 1) ? b1 : b2);
    float*       C    = (z == 0) ? C0 : ((z == 1) ? C1 : C2);

    int w = t >> 5, lane = t & 31;
    int gid = lane >> 2, tig = lane & 3;
    int m0 = blockIdx.x * 128;
    int n0 = blockIdx.y * 64;
    int wm = (w >> 1) * 32;
    int wn = (w & 1) * 32;

    unsigned* sAhi = sm_gemm + SA_HI;
    unsigned* sAlo = sm_gemm + SA_LO;
    unsigned* sWhi = sm_gemm + SW_HI;
    unsigned* sWlo = sm_gemm + SW_LO;

    float acc[2][4][4] = {};

    for (int kk = 0; kk < DIM; kk += 32) {
        __syncthreads();
        // load A tile 128x32 (4 float4/thread), split to bf16 hi/lo pairs
        #pragma unroll
        for (int i = 0; i < 4; i++) {
            int f = t + i * 256;
            int r = f >> 3, c4 = f & 7;
            float4 av = *(const float4*)&A[(size_t)(m0 + r) * DIM + kk + c4 * 4];
            unsigned h0, h1, l0, l1;
            split4_bf16(av, h0, h1, l0, l1);
            *(uint2*)&sAhi[r * GPB + c4 * 2] = make_uint2(h0, h1);
            *(uint2*)&sAlo[r * GPB + c4 * 2] = make_uint2(l0, l1);
        }
        // load W tile 64x32 (2 float4/thread)
        #pragma unroll
        for (int i = 0; i < 2; i++) {
            int f = t + i * 256;
            int r = f >> 3, c4 = f & 7;
            float4 wv = *(const float4*)&W[(size_t)(n0 + r) * DIM + kk + c4 * 4];
            unsigned h0, h1, l0, l1;
            split4_bf16(wv, h0, h1, l0, l1);
            *(uint2*)&sWhi[r * GPB + c4 * 2] = make_uint2(h0, h1);
            *(uint2*)&sWlo[r * GPB + c4 * 2] = make_uint2(l0, l1);
        }
        __syncthreads();

        #pragma unroll
        for (int ksp = 0; ksp < 2; ksp++) {
            int wb = ksp * 8;
            unsigned ah[2][4], al[2][4], bh[4][2], bl[4][2];
            #pragma unroll
            for (int i = 0; i < 2; i++) {
                int mr = wm + i * 16 + gid;
                int c  = wb + tig;
                ah[i][0] = sAhi[mr * GPB + c];
                ah[i][1] = sAhi[(mr + 8) * GPB + c];
                ah[i][2] = sAhi[mr * GPB + c + 4];
                ah[i][3] = sAhi[(mr + 8) * GPB + c + 4];
                al[i][0] = sAlo[mr * GPB + c];
                al[i][1] = sAlo[(mr + 8) * GPB + c];
                al[i][2] = sAlo[mr * GPB + c + 4];
                al[i][3] = sAlo[(mr + 8) * GPB + c + 4];
            }
            #pragma unroll
            for (int j = 0; j < 4; j++) {
                int nr = wn + j * 8 + gid;
                int c  = wb + tig;
                bh[j][0] = sWhi[nr * GPB + c];
                bh[j][1] = sWhi[nr * GPB + c + 4];
                bl[j][0] = sWlo[nr * GPB + c];
                bl[j][1] = sWlo[nr * GPB + c + 4];
            }
            #pragma unroll
            for (int i = 0; i < 2; i++)
                #pragma unroll
                for (int j = 0; j < 4; j++) {
                    mma_bf16(acc[i][j], ah[i], bh[j]);
                    mma_bf16(acc[i][j], ah[i], bl[j]);
                    mma_bf16(acc[i][j], al[i], bh[j]);
                }
        }
    }

    #pragma unroll
    for (int i = 0; i < 2; i++) {
        #pragma unroll
        for (int j = 0; j < 4; j++) {
            int n = n0 + wn + j * 8 + tig * 2;
            float bb0 = __ldg(&bias[n]), bb1 = __ldg(&bias[n + 1]);
            int m = m0 + wm + i * 16 + gid;
            *(float2*)&C[(size_t)m * DIM + n] =
                make_float2(acc[i][j][0] + bb0, acc[i][j][1] + bb1);
            *(float2*)&C[(size_t)(m + 8) * DIM + n] =
                make_float2(acc[i][j][2] + bb0, acc[i][j][3] + bb1);
        }
    }
}

// ---------------- tensor-core block-diagonal attention + fused zero ---------
// grid = (NB, 32 + NZY). y < NZY: zero-fill blocks (NZY per batch, dispatched
// first; block y zeroes rows qs+y, qs+y+NZY, ... outside [ks,ke) — race-free
// vs attn blocks which write every [ks,ke) entry). y >= NZY: attn blocks,
// 32 query rows each, 2xTF32 MMA, software-pipelined cp.async.
#define AP 260
#define VP 264
#define PP 36
#define ATTN_SMEM_F (32 * AP * 2 + 32 * VP + 32 * PP + 32)

extern __shared__ float sm_attn[];

__global__ __launch_bounds__(256)
void attn_mma(const float* __restrict__ Q, const float* __restrict__ K,
              const float* __restrict__ V, float* __restrict__ attn,
              float* __restrict__ O, int Mtot) {
    int b  = blockIdx.x;
    int qs = g_qseg[b], qe = g_qseg[b + 1];
    int ks = g_kseg[b], ke = g_kseg[b + 1];
    int t = threadIdx.x;

    if (blockIdx.y < NZY) {
        // zero-fill: rows qs+y, qs+y+NZY, ...; cols [0,ks) U [ke,Mtot)
        int m4 = Mtot >> 2;
        float4 z4 = make_float4(0.f, 0.f, 0.f, 0.f);
        for (int r = qs + (int)blockIdx.y; r < qe; r += NZY) {
            float* row = attn + (size_t)r * Mtot;
            for (int c4 = t; c4 < m4; c4 += 256) {
                int c = c4 * 4;
                if (c + 4 <= ks || c >= ke) {
                    __stcs((float4*)row + c4, z4);
                } else if (c < ks || c + 4 > ke) {
                    #pragma unroll
                    for (int e = 0; e < 4; e++) {
                        int cc = c + e;
                        if (cc < ks || cc >= ke) __stcs(row + cc, 0.f);
                    }
                }
            }
        }
        return;
    }

    int row0 = qs + ((int)blockIdx.y - NZY) * 32;
    if (row0 >= qe) return;
    int rows = min(32, qe - row0);
    int nk = ke - ks;

    int w = t >> 5, lane = t & 31;
    int gid = lane >> 2, tig = lane & 3;

    float* Qs = sm_attn;
    float* Ks = Qs + 32 * AP;
    float* Vs = Ks + 32 * AP;
    float* Ps = Vs + 32 * VP;
    float* rowsum = Ps + 32 * PP;

    if (nk == 0) {
        for (int i = t; i < rows * DIM; i += 256)
            O[(size_t)row0 * DIM + i] = 0.f;
        return;
    }

    int ntiles = (nk + 31) >> 5;

    // prologue: Q group, K0 group, V0 group; wait for Q+K0 (V0 in flight)
    for (int i = t; i < 32 * 64; i += 256) {
        int r = i >> 6, c4 = i & 63;
        cp16z(&Qs[r * AP + c4 * 4], &Q[(size_t)(row0 + r) * DIM + c4 * 4], r < rows);
    }
    asm volatile("cp.async.commit_group;\n");
    for (int i = t; i < 32 * 64; i += 256) {
        int r = i >> 6, c4 = i & 63;
        cp16z(&Ks[r * AP + c4 * 4], &K[(size_t)(ks + r) * DIM + c4 * 4], r < nk);
    }
    asm volatile("cp.async.commit_group;\n");
    for (int i = t; i < 32 * 64; i += 256) {
        int r = i >> 6, c4 = i & 63;
        cp16z(&Vs[r * VP + c4 * 4], &V[(size_t)(ks + r) * DIM + c4 * 4], r < nk);
    }
    asm volatile("cp.async.commit_group;\n");
    asm volatile("cp.async.wait_group 1;\n" ::: "memory");
    if (t < 32) rowsum[t] = 0.f;

    int mh  = w & 1;
    int wn0 = (w >> 1) * 8;

    float o_acc[2][4][4] = {};

    for (int kt = 0; kt < ntiles; kt++) {
        int kbase = kt << 5;
        bool more = (kt + 1 < ntiles);
        if (kt > 0)
            asm volatile("cp.async.wait_group 1;\n" ::: "memory");  // K[kt] done
        __syncthreads();                 // K[kt] (and Q) visible to all

        // ---- QK^T, 2-pass: Q hi-only, K split ----
        float sacc[4] = {0.f, 0.f, 0.f, 0.f};
        #pragma unroll
        for (int kk = 0; kk < DIM; kk += 8) {
            unsigned ah[4], bh[2], bl[2];
            int c = kk + tig;
            int mr = mh * 16 + gid;
            ah[0] = f2tf32(Qs[mr * AP + c]);
            ah[1] = f2tf32(Qs[(mr + 8) * AP + c]);
            ah[2] = f2tf32(Qs[mr * AP + c + 4]);
            ah[3] = f2tf32(Qs[(mr + 8) * AP + c + 4]);
            int nr = wn0 + gid;
            split_tf32(Ks[nr * AP + c],     bh[0], bl[0]);
            split_tf32(Ks[nr * AP + c + 4], bh[1], bl[1]);
            mma_tf32(sacc, ah, bh);
            mma_tf32(sacc, ah, bl);
        }
        int kn = kbase + wn0 + 2 * tig;
        float e0 = (kn     < nk) ? __expf(sacc[0] * SCALE) : 0.f;
        float e1 = (kn + 1 < nk) ? __expf(sacc[1] * SCALE) : 0.f;
        float e2 = (kn     < nk) ? __expf(sacc[2] * SCALE) : 0.f;
        float e3 = (kn + 1 < nk) ? __expf(sacc[3] * SCALE) : 0.f;
        int pr = mh * 16 + gid;
        Ps[pr * PP + wn0 + 2 * tig]           = e0;
        Ps[pr * PP + wn0 + 2 * tig + 1]       = e1;
        Ps[(pr + 8) * PP + wn0 + 2 * tig]     = e2;
        Ps[(pr + 8) * PP + wn0 + 2 * tig + 1] = e3;
        __syncthreads();                 // P visible; all Ks reads done

        // prefetch K[kt+1] into Ks (hides under rowsum+PV)
        if (more) {
            int kb2 = kbase + 32;
            for (int i = t; i < 32 * 64; i += 256) {
                int r = i >> 6, c4 = i & 63;
                cp16z(&Ks[r * AP + c4 * 4],
                      &K[(size_t)(ks + kb2 + r) * DIM + c4 * 4], kb2 + r < nk);
            }
            asm volatile("cp.async.commit_group;\n");
        }

        // ---- unnormalized attn write + rowsum ----
        #pragma unroll
        for (int i = 0; i < 4; i++) {
            int r = w + i * 8;
            float e = Ps[r * PP + lane];
            float s = e;
            #pragma unroll
            for (int off = 16; off; off >>= 1) s += __shfl_xor_sync(0xFFFFFFFFu, s, off);
            if (lane == 0) rowsum[r] += s;
            if (r < rows && kbase + lane < nk)
                attn[(size_t)(row0 + r) * Mtot + ks + kbase + lane] = e;
        }

        // V[kt] must be complete before PV
        if (more) asm volatile("cp.async.wait_group 1;\n" ::: "memory");
        else      asm volatile("cp.async.wait_group 0;\n" ::: "memory");
        __syncthreads();                 // V[kt] visible to all

        // ---- PV, 2-pass: P hi-only, V split ----
        #pragma unroll
        for (int kk = 0; kk < 32; kk += 8) {
            unsigned pah[2][4];
            int c = kk + tig;
            #pragma unroll
            for (int i = 0; i < 2; i++) {
                int mr = i * 16 + gid;
                pah[i][0] = f2tf32(Ps[mr * PP + c]);
                pah[i][1] = f2tf32(Ps[(mr + 8) * PP + c]);
                pah[i][2] = f2tf32(Ps[mr * PP + c + 4]);
                pah[i][3] = f2tf32(Ps[(mr + 8) * PP + c + 4]);
            }
            #pragma unroll
            for (int j = 0; j < 4; j++) {
                int n = w * 32 + 8 * j + gid;
                unsigned vbh[2], vbl[2];
                split_tf32(Vs[c * VP + n],       vbh[0], vbl[0]);
                split_tf32(Vs[(c + 4) * VP + n], vbh[1], vbl[1]);
                #pragma unroll
                for (int i = 0; i < 2; i++) {
                    mma_tf32(o_acc[i][j], pah[i], vbh);
                    mma_tf32(o_acc[i][j], pah[i], vbl);
                }
            }
        }
        __syncthreads();                 // all Vs reads done

        // prefetch V[kt+1] into Vs (hides under next QK)
        if (more) {
            int kb2 = kbase + 32;
            for (int i = t; i < 32 * 64; i += 256) {
                int r = i >> 6, c4 = i & 63;
                cp16z(&Vs[r * VP + c4 * 4],
                      &V[(size_t)(ks + kb2 + r) * DIM + c4 * 4], kb2 + r < nk);
            }
            asm volatile("cp.async.commit_group;\n");
        }
    }
    __syncthreads();
    if (t < 32) rowsum[t] = (rowsum[t] > 0.f) ? (1.f / rowsum[t]) : 0.f;
    __syncthreads();

    // normalize attn in place (warp-per-row, coalesced)
    #pragma unroll
    for (int i = 0; i < 4; i++) {
        int r = w + i * 8;
        if (r < rows) {
            float inv = rowsum[r];
            size_t base = (size_t)(row0 + r) * Mtot + ks;
            for (int j = lane; j < nk; j += 32) attn[base + j] *= inv;
        }
    }
    #pragma unroll
    for (int i = 0; i < 2; i++) {
        int r = i * 16 + gid;
        if (r < rows) {
            float inv = rowsum[r];
            #pragma unroll
            for (int j = 0; j < 4; j++) {
                int n = w * 32 + 8 * j + 2 * tig;
                *(float2*)&O[(size_t)(row0 + r) * DIM + n] =
                    make_float2(o_acc[i][j][0] * inv, o_acc[i][j][1] * inv);
            }
        }
        int r8 = r + 8;
        if (r8 < rows) {
            float inv = rowsum[r8];
            #pragma unroll
            for (int j = 0; j < 4; j++) {
                int n = w * 32 + 8 * j + 2 * tig;
                *(float2*)&O[(size_t)(row0 + r8) * DIM + n] =
                    make_float2(o_acc[i][j][2] * inv, o_acc[i][j][3] * inv);
            }
        }
    }
}

// ---------------- launch (single stream, no events) -------------------------
extern "C" void kernel_launch(void* const* d_in, const int* in_sizes, int n_in,
                              void* d_out, int out_size) {
    const float* q_feat = (const float*)d_in[0];
    const float* k_feat = (const float*)d_in[1];
    const int*   q_batch = (const int*)d_in[2];
    const int*   k_batch = (const int*)d_in[3];
    const float* Wq = (const float*)d_in[4];
    const float* bq = (const float*)d_in[5];
    const float* Wk = (const float*)d_in[6];
    const float* bk = (const float*)d_in[7];
    const float* Wv = (const float*)d_in[8];
    const float* bv = (const float*)d_in[9];
    const float* Wo = (const float*)d_in[10];
    const float* bo = (const float*)d_in[11];

    int n = in_sizes[0] / DIM;
    int m = in_sizes[1] / DIM;

    float* out      = (float*)d_out;
    float* attended = out;                        // [n, DIM]
    float* attn     = out + (size_t)n * DIM;      // [n, m]

    float *Qd, *Kd, *Vd, *Od;
    cudaGetSymbolAddress((void**)&Qd, g_Q);
    cudaGetSymbolAddress((void**)&Kd, g_K);
    cudaGetSymbolAddress((void**)&Vd, g_V);
    cudaGetSymbolAddress((void**)&Od, g_O);

    const size_t attn_smem = ATTN_SMEM_F * sizeof(float);
    const size_t gemm_smem = GEMM_SMEM_U32 * sizeof(unsigned);
    cudaFuncSetAttribute(attn_mma, cudaFuncAttributeMaxDynamicSharedMemorySize,
                         (int)attn_smem);
    cudaFuncSetAttribute(gemm3_bf16, cudaFuncAttributeMaxDynamicSharedMemorySize,
                         (int)gemm_smem);

    // 1. fused QKV projection (bf16 3-pass GEMM) + segment boundaries
    gemm3_bf16<<<dim3(n / 128, 4, 3), 256, gemm_smem>>>(
        q_feat, k_feat, Wq, bq, Wk, bk, Wv, bv, Qd, Kd, Vd,
        q_batch, k_batch, n, m);
    // 2. attention + fused zero-fill (512 zero blocks dispatch first)
    attn_mma<<<dim3(NB, 32 + NZY), 256, attn_smem>>>(Qd, Kd, Vd, attn, Od, m);
    // 3. output projection
    gemm3_bf16<<<dim3(n / 128, 4, 1), 256, gemm_smem>>>(
        Od, Od, Wo, bo, Wo, bo, Wo, bo, attended, attended, attended,
        nullptr, nullptr, 0, 0);
}

// round 16
// speedup vs baseline: 1.2508x; 1.0375x over previous
#include <cuda_runtime.h>
#include <cstdint>

#define NQMAX 8192
#define DIM   256
#define NB    64
#define SCALE 0.0625f   /* 1/sqrt(256) exactly */
#define NZY   8         /* zero slices per batch in the attn launch */

// ---------------- scratch (device globals: allocation-free) ----------------
__device__ float g_Q[NQMAX * DIM];
__device__ float g_K[NQMAX * DIM];
__device__ float g_V[NQMAX * DIM];
__device__ float g_O[NQMAX * DIM];
__device__ int   g_qseg[NB + 1];
__device__ int   g_kseg[NB + 1];

// ---------------- tf32 / bf16 / mma helpers --------------------------------
__device__ __forceinline__ unsigned f2tf32(float x) {
    unsigned r;
    asm("cvt.rna.tf32.f32 %0, %1;" : "=r"(r) : "f"(x));
    return r;
}
__device__ __forceinline__ void split_tf32(float x, unsigned& hi, unsigned& lo) {
    hi = f2tf32(x);
    lo = f2tf32(x - __uint_as_float(hi));
}
// pack {lo-half = bf16(x), hi-half = bf16(y)}  (PTX: first source -> high)
__device__ __forceinline__ unsigned pack_bf16x2(float x, float y) {
    unsigned r;
    asm("cvt.rn.bf16x2.f32 %0, %1, %2;" : "=r"(r) : "f"(y), "f"(x));
    return r;
}
// tf32 mma m16n8k8 (attn path)
__device__ __forceinline__ void mma_tf32(float* d, const unsigned* a, const unsigned* b) {
    asm volatile(
        "mma.sync.aligned.m16n8k8.row.col.f32.tf32.tf32.f32 "
        "{%0,%1,%2,%3}, {%4,%5,%6,%7}, {%8,%9}, {%0,%1,%2,%3};\n"
        : "+f"(d[0]), "+f"(d[1]), "+f"(d[2]), "+f"(d[3])
        : "r"(a[0]), "r"(a[1]), "r"(a[2]), "r"(a[3]), "r"(b[0]), "r"(b[1]));
}
// bf16 mma m16n8k16 (GEMM path) — same register shape, 2x work per instr
__device__ __forceinline__ void mma_bf16(float* d, const unsigned* a, const unsigned* b) {
    asm volatile(
        "mma.sync.aligned.m16n8k16.row.col.f32.bf16.bf16.f32 "
        "{%0,%1,%2,%3}, {%4,%5,%6,%7}, {%8,%9}, {%0,%1,%2,%3};\n"
        : "+f"(d[0]), "+f"(d[1]), "+f"(d[2]), "+f"(d[3])
        : "r"(a[0]), "r"(a[1]), "r"(a[2]), "r"(a[3]), "r"(b[0]), "r"(b[1]));
}
__device__ __forceinline__ void cp16z(void* s, const void* g, bool p) {
    unsigned sa = (unsigned)__cvta_generic_to_shared(s);
    int sz = p ? 16 : 0;
    asm volatile("cp.async.cg.shared.global [%0], [%1], 16, %2;\n"
                 :: "r"(sa), "l"(g), "r"(sz));
}
// split a float4 into bf16x2 hi-words and lo-residual words (k-pairs)
__device__ __forceinline__ void split4_bf16(float4 v, unsigned& h0, unsigned& h1,
                                            unsigned& l0, unsigned& l1) {
    h0 = pack_bf16x2(v.x, v.y);
    h1 = pack_bf16x2(v.z, v.w);
    float hx = __uint_as_float(h0 << 16);
    float hy = __uint_as_float(h0 & 0xffff0000u);
    float hz = __uint_as_float(h1 << 16);
    float hw = __uint_as_float(h1 & 0xffff0000u);
    l0 = pack_bf16x2(v.x - hx, v.y - hy);
    l1 = pack_bf16x2(v.z - hz, v.w - hw);
}

// ---------------- GEMM: C[Mr,256] = A[Mr,256] @ W[256,256]^T + bias --------
// 3-pass bf16 (hi*hi + hi*lo + lo*hi) on m16n8k16 (unchanged from R15).
#define GPB 20
#define SA_HI 0
#define SA_LO (128 * GPB)
#define SW_HI (2 * 128 * GPB)
#define SW_LO (2 * 128 * GPB + 64 * GPB)
#define GEMM_SMEM_U32 (2 * 128 * GPB + 2 * 64 * GPB)   /* 30720 bytes */

extern __shared__ unsigned sm_gemm[];

__global__ __launch_bounds__(256, 3)
void gemm3_bf16(const float* __restrict__ A0, const float* __restrict__ A12,
                const float* __restrict__ W0, const float* __restrict__ b0,
                const float* __restrict__ W1, const float* __restrict__ b1,
                const float* __restrict__ W2, const float* __restrict__ b2,
                float* __restrict__ C0, float* __restrict__ C1, float* __restrict__ C2,
                const int* __restrict__ qb, const int* __restrict__ kb,
                int nq, int mk) {
    int t = threadIdx.x;

    // segment boundaries (one block, runs before its GEMM work)
    if (qb != nullptr && blockIdx.x == 0 && blockIdx.y == 0 && blockIdx.z == 0
        && t <= NB) {
        int b = t;
        int lo = 0, hi = nq;
        while (lo < hi) { int mid = (lo + hi) >> 1; if (qb[mid] < b) lo = mid + 1; else hi = mid; }
        g_qseg[b] = lo;
        lo = 0; hi = mk;
        while (lo < hi) { int mid = (lo + hi) >> 1; if (kb[mid] < b) lo = mid + 1; else hi = mid; }
        g_kseg[b] = lo;
    }

    int z = blockIdx.z;
    const float* A    = (z == 0) ? A0 : A12;
    const float* W    = (z == 0) ? W0 : ((z == 1) ? W1 : W2);
    const float* bias = (z == 0) ? b0 : ((z == 1) ? b1 : b2);
    float*       C    = (z == 0) ? C0 : ((z == 1) ? C1 : C2);

    int w = t >> 5, lane = t & 31;
    int gid = lane >> 2, tig = lane & 3;
    int m0 = blockIdx.x * 128;
    int n0 = blockIdx.y * 64;
    int wm = (w >> 1) * 32;
    int wn = (w & 1) * 32;

    unsigned* sAhi = sm_gemm + SA_HI;
    unsigned* sAlo = sm_gemm + SA_LO;
    unsigned* sWhi = sm_gemm + SW_HI;
    unsigned* sWlo = sm_gemm + SW_LO;

    float acc[2][4][4] = {};

    for (int kk = 0; kk < DIM; kk += 32) {
        __syncthreads();
        // load A tile 128x32 (4 float4/thread), split to bf16 hi/lo pairs
        #pragma unroll
        for (int i = 0; i < 4; i++) {
            int f = t + i * 256;
            int r = f >> 3, c4 = f & 7;
            float4 av = *(const float4*)&A[(size_t)(m0 + r) * DIM + kk + c4 * 4];
            unsigned h0, h1, l0, l1;
            split4_bf16(av, h0, h1, l0, l1);
            *(uint2*)&sAhi[r * GPB + c4 * 2] = make_uint2(h0, h1);
            *(uint2*)&sAlo[r * GPB + c4 * 2] = make_uint2(l0, l1);
        }
        // load W tile 64x32 (2 float4/thread)
        #pragma unroll
        for (int i = 0; i < 2; i++) {
            int f = t + i * 256;
            int r = f >> 3, c4 = f & 7;
            float4 wv = *(const float4*)&W[(size_t)(n0 + r) * DIM + kk + c4 * 4];
            unsigned h0, h1, l0, l1;
            split4_bf16(wv, h0, h1, l0, l1);
            *(uint2*)&sWhi[r * GPB + c4 * 2] = make_uint2(h0, h1);
            *(uint2*)&sWlo[r * GPB + c4 * 2] = make_uint2(l0, l1);
        }
        __syncthreads();

        #pragma unroll
        for (int ksp = 0; ksp < 2; ksp++) {
            int wb = ksp * 8;
            unsigned ah[2][4], al[2][4], bh[4][2], bl[4][2];
            #pragma unroll
            for (int i = 0; i < 2; i++) {
                int mr = wm + i * 16 + gid;
                int c  = wb + tig;
                ah[i][0] = sAhi[mr * GPB + c];
                ah[i][1] = sAhi[(mr + 8) * GPB + c];
                ah[i][2] = sAhi[mr * GPB + c + 4];
                ah[i][3] = sAhi[(mr + 8) * GPB + c + 4];
                al[i][0] = sAlo[mr * GPB + c];
                al[i][1] = sAlo[(mr + 8) * GPB + c];
                al[i][2] = sAlo[mr * GPB + c + 4];
                al[i][3] = sAlo[(mr + 8) * GPB + c + 4];
            }
            #pragma unroll
            for (int j = 0; j < 4; j++) {
                int nr = wn + j * 8 + gid;
                int c  = wb + tig;
                bh[j][0] = sWhi[nr * GPB + c];
                bh[j][1] = sWhi[nr * GPB + c + 4];
                bl[j][0] = sWlo[nr * GPB + c];
                bl[j][1] = sWlo[nr * GPB + c + 4];
            }
            #pragma unroll
            for (int i = 0; i < 2; i++)
                #pragma unroll
                for (int j = 0; j < 4; j++) {
                    mma_bf16(acc[i][j], ah[i], bh[j]);
                    mma_bf16(acc[i][j], ah[i], bl[j]);
                    mma_bf16(acc[i][j], al[i], bh[j]);
                }
        }
    }

    #pragma unroll
    for (int i = 0; i < 2; i++) {
        #pragma unroll
        for (int j = 0; j < 4; j++) {
            int n = n0 + wn + j * 8 + tig * 2;
            float bb0 = __ldg(&bias[n]), bb1 = __ldg(&bias[n + 1]);
            int m = m0 + wm + i * 16 + gid;
            *(float2*)&C[(size_t)m * DIM + n] =
                make_float2(acc[i][j][0] + bb0, acc[i][j][1] + bb1);
            *(float2*)&C[(size_t)(m + 8) * DIM + n] =
                make_float2(acc[i][j][2] + bb0, acc[i][j][3] + bb1);
        }
    }
}

// ---------------- tensor-core block-diagonal attention + fused zero ---------
// grid = (NB, 40). INTERLEAVED dispatch (x-major order => y order is launch
// order): y % 5 == 0 -> zero slice zi = y/5 (8 per batch); else attn block
// ai = y - y/5 - 1 (0..31). This keeps store-heavy zero blocks and
// issue-heavy attn blocks co-resident (R15 front-loaded all 512 zero blocks,
// which filled the machine and serialized zero before attn).
#define AP 260
#define VP 264
#define PP 36
#define ATTN_SMEM_F (32 * AP * 2 + 32 * VP + 32 * PP + 32)

extern __shared__ float sm_attn[];

__global__ __launch_bounds__(256)
void attn_mma(const float* __restrict__ Q, const float* __restrict__ K,
              const float* __restrict__ V, float* __restrict__ attn,
              float* __restrict__ O, int Mtot) {
    int b  = blockIdx.x;
    int qs = g_qseg[b], qe = g_qseg[b + 1];
    int ks = g_kseg[b], ke = g_kseg[b + 1];
    int t = threadIdx.x;
    int y = (int)blockIdx.y;

    if (y % 5 == 0) {
        // zero-fill slice zi: rows qs+zi, qs+zi+NZY, ...; cols outside [ks,ke)
        int zi = y / 5;
        int m4 = Mtot >> 2;
        float4 z4 = make_float4(0.f, 0.f, 0.f, 0.f);
        for (int r = qs + zi; r < qe; r += NZY) {
            float* row = attn + (size_t)r * Mtot;
            for (int c4 = t; c4 < m4; c4 += 256) {
                int c = c4 * 4;
                if (c + 4 <= ks || c >= ke) {
                    __stcs((float4*)row + c4, z4);
                } else if (c < ks || c + 4 > ke) {
                    #pragma unroll
                    for (int e = 0; e < 4; e++) {
                        int cc = c + e;
                        if (cc < ks || cc >= ke) __stcs(row + cc, 0.f);
                    }
                }
            }
        }
        return;
    }

    int ai = y - y / 5 - 1;          // 0..31
    int row0 = qs + ai * 32;
    if (row0 >= qe) return;
    int rows = min(32, qe - row0);
    int nk = ke - ks;

    int w = t >> 5, lane = t & 31;
    int gid = lane >> 2, tig = lane & 3;

    float* Qs = sm_attn;
    float* Ks = Qs + 32 * AP;
    float* Vs = Ks + 32 * AP;
    float* Ps = Vs + 32 * VP;
    float* rowsum = Ps + 32 * PP;

    if (nk == 0) {
        for (int i = t; i < rows * DIM; i += 256)
            O[(size_t)row0 * DIM + i] = 0.f;
        return;
    }

    int ntiles = (nk + 31) >> 5;

    // prologue: Q group, K0 group, V0 group; wait for Q+K0 (V0 in flight)
    for (int i = t; i < 32 * 64; i += 256) {
        int r = i >> 6, c4 = i & 63;
        cp16z(&Qs[r * AP + c4 * 4], &Q[(size_t)(row0 + r) * DIM + c4 * 4], r < rows);
    }
    asm volatile("cp.async.commit_group;\n");
    for (int i = t; i < 32 * 64; i += 256) {
        int r = i >> 6, c4 = i & 63;
        cp16z(&Ks[r * AP + c4 * 4], &K[(size_t)(ks + r) * DIM + c4 * 4], r < nk);
    }
    asm volatile("cp.async.commit_group;\n");
    for (int i = t; i < 32 * 64; i += 256) {
        int r = i >> 6, c4 = i & 63;
        cp16z(&Vs[r * VP + c4 * 4], &V[(size_t)(ks + r) * DIM + c4 * 4], r < nk);
    }
    asm volatile("cp.async.commit_group;\n");
    asm volatile("cp.async.wait_group 1;\n" ::: "memory");
    if (t < 32) rowsum[t] = 0.f;

    int mh  = w & 1;
    int wn0 = (w >> 1) * 8;

    float o_acc[2][4][4] = {};

    for (int kt = 0; kt < ntiles; kt++) {
        int kbase = kt << 5;
        bool more = (kt + 1 < ntiles);
        if (kt > 0)
            asm volatile("cp.async.wait_group 1;\n" ::: "memory");  // K[kt] done
        __syncthreads();                 // K[kt] (and Q) visible to all

        // ---- QK^T, 2-pass: Q hi-only, K split ----
        float sacc[4] = {0.f, 0.f, 0.f, 0.f};
        #pragma unroll
        for (int kk = 0; kk < DIM; kk += 8) {
            unsigned ah[4], bh[2], bl[2];
            int c = kk + tig;
            int mr = mh * 16 + gid;
            ah[0] = f2tf32(Qs[mr * AP + c]);
            ah[1] = f2tf32(Qs[(mr + 8) * AP + c]);
            ah[2] = f2tf32(Qs[mr * AP + c + 4]);
            ah[3] = f2tf32(Qs[(mr + 8) * AP + c + 4]);
            int nr = wn0 + gid;
            split_tf32(Ks[nr * AP + c],     bh[0], bl[0]);
            split_tf32(Ks[nr * AP + c + 4], bh[1], bl[1]);
            mma_tf32(sacc, ah, bh);
            mma_tf32(sacc, ah, bl);
        }
        int kn = kbase + wn0 + 2 * tig;
        float e0 = (kn     < nk) ? __expf(sacc[0] * SCALE) : 0.f;
        float e1 = (kn + 1 < nk) ? __expf(sacc[1] * SCALE) : 0.f;
        float e2 = (kn     < nk) ? __expf(sacc[2] * SCALE) : 0.f;
        float e3 = (kn + 1 < nk) ? __expf(sacc[3] * SCALE) : 0.f;
        int pr = mh * 16 + gid;
        Ps[pr * PP + wn0 + 2 * tig]           = e0;
        Ps[pr * PP + wn0 + 2 * tig + 1]       = e1;
        Ps[(pr + 8) * PP + wn0 + 2 * tig]     = e2;
        Ps[(pr + 8) * PP + wn0 + 2 * tig + 1] = e3;
        __syncthreads();                 // P visible; all Ks reads done

        // prefetch K[kt+1] into Ks (hides under rowsum+PV)
        if (more) {
            int kb2 = kbase + 32;
            for (int i = t; i < 32 * 64; i += 256) {
                int r = i >> 6, c4 = i & 63;
                cp16z(&Ks[r * AP + c4 * 4],
                      &K[(size_t)(ks + kb2 + r) * DIM + c4 * 4], kb2 + r < nk);
            }
            asm volatile("cp.async.commit_group;\n");
        }

        // ---- unnormalized attn write + rowsum ----
        #pragma unroll
        for (int i = 0; i < 4; i++) {
            int r = w + i * 8;
            float e = Ps[r * PP + lane];
            float s = e;
            #pragma unroll
            for (int off = 16; off; off >>= 1) s += __shfl_xor_sync(0xFFFFFFFFu, s, off);
            if (lane == 0) rowsum[r] += s;
            if (r < rows && kbase + lane < nk)
                attn[(size_t)(row0 + r) * Mtot + ks + kbase + lane] = e;
        }

        // V[kt] must be complete before PV
        if (more) asm volatile("cp.async.wait_group 1;\n" ::: "memory");
        else      asm volatile("cp.async.wait_group 0;\n" ::: "memory");
        __syncthreads();                 // V[kt] visible to all

        // ---- PV, 2-pass: P hi-only, V split ----
        #pragma unroll
        for (int kk = 0; kk < 32; kk += 8) {
            unsigned pah[2][4];
            int c = kk + tig;
            #pragma unroll
            for (int i = 0; i < 2; i++) {
                int mr = i * 16 + gid;
                pah[i][0] = f2tf32(Ps[mr * PP + c]);
                pah[i][1] = f2tf32(Ps[(mr + 8) * PP + c]);
                pah[i][2] = f2tf32(Ps[mr * PP + c + 4]);
                pah[i][3] = f2tf32(Ps[(mr + 8) * PP + c + 4]);
            }
            #pragma unroll
            for (int j = 0; j < 4; j++) {
                int n = w * 32 + 8 * j + gid;
                unsigned vbh[2], vbl[2];
                split_tf32(Vs[c * VP + n],       vbh[0], vbl[0]);
                split_tf32(Vs[(c + 4) * VP + n], vbh[1], vbl[1]);
                #pragma unroll
                for (int i = 0; i < 2; i++) {
                    mma_tf32(o_acc[i][j], pah[i], vbh);
                    mma_tf32(o_acc[i][j], pah[i], vbl);
                }
            }
        }
        __syncthreads();                 // all Vs reads done

        // prefetch V[kt+1] into Vs (hides under next QK)
        if (more) {
            int kb2 = kbase + 32;
            for (int i = t; i < 32 * 64; i += 256) {
                int r = i >> 6, c4 = i & 63;
                cp16z(&Vs[r * VP + c4 * 4],
                      &V[(size_t)(ks + kb2 + r) * DIM + c4 * 4], kb2 + r < nk);
            }
            asm volatile("cp.async.commit_group;\n");
        }
    }
    __syncthreads();
    if (t < 32) rowsum[t] = (rowsum[t] > 0.f) ? (1.f / rowsum[t]) : 0.f;
    __syncthreads();

    // normalize attn in place (warp-per-row, coalesced)
    #pragma unroll
    for (int i = 0; i < 4; i++) {
        int r = w + i * 8;
        if (r < rows) {
            float inv = rowsum[r];
            size_t base = (size_t)(row0 + r) * Mtot + ks;
            for (int j = lane; j < nk; j += 32) attn[base + j] *= inv;
        }
    }
    #pragma unroll
    for (int i = 0; i < 2; i++) {
        int r = i * 16 + gid;
        if (r < rows) {
            float inv = rowsum[r];
            #pragma unroll
            for (int j = 0; j < 4; j++) {
                int n = w * 32 + 8 * j + 2 * tig;
                *(float2*)&O[(size_t)(row0 + r) * DIM + n] =
                    make_float2(o_acc[i][j][0] * inv, o_acc[i][j][1] * inv);
            }
        }
        int r8 = r + 8;
        if (r8 < rows) {
            float inv = rowsum[r8];
            #pragma unroll
            for (int j = 0; j < 4; j++) {
                int n = w * 32 + 8 * j + 2 * tig;
                *(float2*)&O[(size_t)(row0 + r8) * DIM + n] =
                    make_float2(o_acc[i][j][2] * inv, o_acc[i][j][3] * inv);
            }
        }
    }
}

// ---------------- launch (single stream, no events) -------------------------
extern "C" void kernel_launch(void* const* d_in, const int* in_sizes, int n_in,
                              void* d_out, int out_size) {
    const float* q_feat = (const float*)d_in[0];
    const float* k_feat = (const float*)d_in[1];
    const int*   q_batch = (const int*)d_in[2];
    const int*   k_batch = (const int*)d_in[3];
    const float* Wq = (const float*)d_in[4];
    const float* bq = (const float*)d_in[5];
    const float* Wk = (const float*)d_in[6];
    const float* bk = (const float*)d_in[7];
    const float* Wv = (const float*)d_in[8];
    const float* bv = (const float*)d_in[9];
    const float* Wo = (const float*)d_in[10];
    const float* bo = (const float*)d_in[11];

    int n = in_sizes[0] / DIM;
    int m = in_sizes[1] / DIM;

    float* out      = (float*)d_out;
    float* attended = out;                        // [n, DIM]
    float* attn     = out + (size_t)n * DIM;      // [n, m]

    float *Qd, *Kd, *Vd, *Od;
    cudaGetSymbolAddress((void**)&Qd, g_Q);
    cudaGetSymbolAddress((void**)&Kd, g_K);
    cudaGetSymbolAddress((void**)&Vd, g_V);
    cudaGetSymbolAddress((void**)&Od, g_O);

    const size_t attn_smem = ATTN_SMEM_F * sizeof(float);
    const size_t gemm_smem = GEMM_SMEM_U32 * sizeof(unsigned);
    cudaFuncSetAttribute(attn_mma, cudaFuncAttributeMaxDynamicSharedMemorySize,
                         (int)attn_smem);
    cudaFuncSetAttribute(gemm3_bf16, cudaFuncAttributeMaxDynamicSharedMemorySize,
                         (int)gemm_smem);

    // 1. fused QKV projection (bf16 3-pass GEMM) + segment boundaries
    gemm3_bf16<<<dim3(n / 128, 4, 3), 256, gemm_smem>>>(
        q_feat, k_feat, Wq, bq, Wk, bk, Wv, bv, Qd, Kd, Vd,
        q_batch, k_batch, n, m);
    // 2. attention + fused zero-fill, INTERLEAVED dispatch (y%5==0 -> zero)
    attn_mma<<<dim3(NB, 40), 256, attn_smem>>>(Qd, Kd, Vd, attn, Od, m);
    // 3. output projection
    gemm3_bf16<<<dim3(n / 128, 4, 1), 256, gemm_smem>>>(
        Od, Od, Wo, bo, Wo, bo, Wo, bo, attended, attended, attended,
        nullptr, nullptr, 0, 0);
}

// round 17
// speedup vs baseline: 1.3083x; 1.0460x over previous
#include <cuda_runtime.h>
#include <cstdint>

#define NQMAX 8192
#define DIM   256
#define NB    64
#define SCALE 0.0625f   /* 1/sqrt(256) exactly */

// ---------------- scratch (device globals: allocation-free) ----------------
__device__ float g_Q[NQMAX * DIM];
__device__ float g_K[NQMAX * DIM];
__device__ float g_V[NQMAX * DIM];
__device__ float g_O[NQMAX * DIM];
__device__ int   g_qseg[NB + 1];
__device__ int   g_kseg[NB + 1];

// ---------------- tf32 / bf16 / mma helpers --------------------------------
__device__ __forceinline__ unsigned f2tf32(float x) {
    unsigned r;
    asm("cvt.rna.tf32.f32 %0, %1;" : "=r"(r) : "f"(x));
    return r;
}
__device__ __forceinline__ void split_tf32(float x, unsigned& hi, unsigned& lo) {
    hi = f2tf32(x);
    lo = f2tf32(x - __uint_as_float(hi));
}
// pack {lo-half = bf16(x), hi-half = bf16(y)}  (PTX: first source -> high)
__device__ __forceinline__ unsigned pack_bf16x2(float x, float y) {
    unsigned r;
    asm("cvt.rn.bf16x2.f32 %0, %1, %2;" : "=r"(r) : "f"(y), "f"(x));
    return r;
}
// tf32 mma m16n8k8 (attn path)
__device__ __forceinline__ void mma_tf32(float* d, const unsigned* a, const unsigned* b) {
    asm volatile(
        "mma.sync.aligned.m16n8k8.row.col.f32.tf32.tf32.f32 "
        "{%0,%1,%2,%3}, {%4,%5,%6,%7}, {%8,%9}, {%0,%1,%2,%3};\n"
        : "+f"(d[0]), "+f"(d[1]), "+f"(d[2]), "+f"(d[3])
        : "r"(a[0]), "r"(a[1]), "r"(a[2]), "r"(a[3]), "r"(b[0]), "r"(b[1]));
}
// bf16 mma m16n8k16 (GEMM path) — same register shape, 2x work per instr
__device__ __forceinline__ void mma_bf16(float* d, const unsigned* a, const unsigned* b) {
    asm volatile(
        "mma.sync.aligned.m16n8k16.row.col.f32.bf16.bf16.f32 "
        "{%0,%1,%2,%3}, {%4,%5,%6,%7}, {%8,%9}, {%0,%1,%2,%3};\n"
        : "+f"(d[0]), "+f"(d[1]), "+f"(d[2]), "+f"(d[3])
        : "r"(a[0]), "r"(a[1]), "r"(a[2]), "r"(a[3]), "r"(b[0]), "r"(b[1]));
}
__device__ __forceinline__ void cp16z(void* s, const void* g, bool p) {
    unsigned sa = (unsigned)__cvta_generic_to_shared(s);
    int sz = p ? 16 : 0;
    asm volatile("cp.async.cg.shared.global [%0], [%1], 16, %2;\n"
                 :: "r"(sa), "l"(g), "r"(sz));
}
// split a float4 into bf16x2 hi-words and lo-residual words (k-pairs)
__device__ __forceinline__ void split4_bf16(float4 v, unsigned& h0, unsigned& h1,
                                            unsigned& l0, unsigned& l1) {
    h0 = pack_bf16x2(v.x, v.y);
    h1 = pack_bf16x2(v.z, v.w);
    float hx = __uint_as_float(h0 << 16);
    float hy = __uint_as_float(h0 & 0xffff0000u);
    float hz = __uint_as_float(h1 << 16);
    float hw = __uint_as_float(h1 & 0xffff0000u);
    l0 = pack_bf16x2(v.x - hx, v.y - hy);
    l1 = pack_bf16x2(v.z - hz, v.w - hw);
}

// ---------------- GEMM: C[Mr,256] = A[Mr,256] @ W[256,256]^T + bias --------
// 3-pass bf16 (hi*hi + hi*lo + lo*hi) on m16n8k16 (unchanged from R15/R16).
#define GPB 20
#define SA_HI 0
#define SA_LO (128 * GPB)
#define SW_HI (2 * 128 * GPB)
#define SW_LO (2 * 128 * GPB + 64 * GPB)
#define GEMM_SMEM_U32 (2 * 128 * GPB + 2 * 64 * GPB)   /* 30720 bytes */

extern __shared__ unsigned sm_gemm[];

__global__ __launch_bounds__(256, 3)
void gemm3_bf16(const float* __restrict__ A0, const float* __restrict__ A12,
                const float* __restrict__ W0, const float* __restrict__ b0,
                const float* __restrict__ W1, const float* __restrict__ b1,
                const float* __restrict__ W2, const float* __restrict__ b2,
                float* __restrict__ C0, float* __restrict__ C1, float* __restrict__ C2,
                const int* __restrict__ qb, const int* __restrict__ kb,
                int nq, int mk) {
    int t = threadIdx.x;

    // segment boundaries (one block, runs before its GEMM work)
    if (qb != nullptr && blockIdx.x == 0 && blockIdx.y == 0 && blockIdx.z == 0
        && t <= NB) {
        int b = t;
        int lo = 0, hi = nq;
        while (lo < hi) { int mid = (lo + hi) >> 1; if (qb[mid] < b) lo = mid + 1; else hi = mid; }
        g_qseg[b] = lo;
        lo = 0; hi = mk;
        while (lo < hi) { int mid = (lo + hi) >> 1; if (kb[mid] < b) lo = mid + 1; else hi = mid; }
        g_kseg[b] = lo;
    }

    int z = blockIdx.z;
    const float* A    = (z == 0) ? A0 : A12;
    const float* W    = (z == 0) ? W0 : ((z == 1) ? W1 : W2);
    const float* bias = (z == 0) ? b0 : ((z == 1) ? b1 : b2);
    float*       C    = (z == 0) ? C0 : ((z == 1) ? C1 : C2);

    int w = t >> 5, lane = t & 31;
    int gid = lane >> 2, tig = lane & 3;
    int m0 = blockIdx.x * 128;
    int n0 = blockIdx.y * 64;
    int wm = (w >> 1) * 32;
    int wn = (w & 1) * 32;

    unsigned* sAhi = sm_gemm + SA_HI;
    unsigned* sAlo = sm_gemm + SA_LO;
    unsigned* sWhi = sm_gemm + SW_HI;
    unsigned* sWlo = sm_gemm + SW_LO;

    float acc[2][4][4] = {};

    for (int kk = 0; kk < DIM; kk += 32) {
        __syncthreads();
        // load A tile 128x32 (4 float4/thread), split to bf16 hi/lo pairs
        #pragma unroll
        for (int i = 0; i < 4; i++) {
            int f = t + i * 256;
            int r = f >> 3, c4 = f & 7;
            float4 av = *(const float4*)&A[(size_t)(m0 + r) * DIM + kk + c4 * 4];
            unsigned h0, h1, l0, l1;
            split4_bf16(av, h0, h1, l0, l1);
            *(uint2*)&sAhi[r * GPB + c4 * 2] = make_uint2(h0, h1);
            *(uint2*)&sAlo[r * GPB + c4 * 2] = make_uint2(l0, l1);
        }
        // load W tile 64x32 (2 float4/thread)
        #pragma unroll
        for (int i = 0; i < 2; i++) {
            int f = t + i * 256;
            int r = f >> 3, c4 = f & 7;
            float4 wv = *(const float4*)&W[(size_t)(n0 + r) * DIM + kk + c4 * 4];
            unsigned h0, h1, l0, l1;
            split4_bf16(wv, h0, h1, l0, l1);
            *(uint2*)&sWhi[r * GPB + c4 * 2] = make_uint2(h0, h1);
            *(uint2*)&sWlo[r * GPB + c4 * 2] = make_uint2(l0, l1);
        }
        __syncthreads();

        #pragma unroll
        for (int ksp = 0; ksp < 2; ksp++) {
            int wb = ksp * 8;
            unsigned ah[2][4], al[2][4], bh[4][2], bl[4][2];
            #pragma unroll
            for (int i = 0; i < 2; i++) {
                int mr = wm + i * 16 + gid;
                int c  = wb + tig;
                ah[i][0] = sAhi[mr * GPB + c];
                ah[i][1] = sAhi[(mr + 8) * GPB + c];
                ah[i][2] = sAhi[mr * GPB + c + 4];
                ah[i][3] = sAhi[(mr + 8) * GPB + c + 4];
                al[i][0] = sAlo[mr * GPB + c];
                al[i][1] = sAlo[(mr + 8) * GPB + c];
                al[i][2] = sAlo[mr * GPB + c + 4];
                al[i][3] = sAlo[(mr + 8) * GPB + c + 4];
            }
            #pragma unroll
            for (int j = 0; j < 4; j++) {
                int nr = wn + j * 8 + gid;
                int c  = wb + tig;
                bh[j][0] = sWhi[nr * GPB + c];
                bh[j][1] = sWhi[nr * GPB + c + 4];
                bl[j][0] = sWlo[nr * GPB + c];
                bl[j][1] = sWlo[nr * GPB + c + 4];
            }
            #pragma unroll
            for (int i = 0; i < 2; i++)
                #pragma unroll
                for (int j = 0; j < 4; j++) {
                    mma_bf16(acc[i][j], ah[i], bh[j]);
                    mma_bf16(acc[i][j], ah[i], bl[j]);
                    mma_bf16(acc[i][j], al[i], bh[j]);
                }
        }
    }

    #pragma unroll
    for (int i = 0; i < 2; i++) {
        #pragma unroll
        for (int j = 0; j < 4; j++) {
            int n = n0 + wn + j * 8 + tig * 2;
            float bb0 = __ldg(&bias[n]), bb1 = __ldg(&bias[n + 1]);
            int m = m0 + wm + i * 16 + gid;
            *(float2*)&C[(size_t)m * DIM + n] =
                make_float2(acc[i][j][0] + bb0, acc[i][j][1] + bb1);
            *(float2*)&C[(size_t)(m + 8) * DIM + n] =
                make_float2(acc[i][j][2] + bb0, acc[i][j][3] + bb1);
        }
    }
}

// ---------------- tensor-core block-diagonal attention + in-block zero ------
// grid = (NB, 32). No dedicated zero blocks: each attn block zeroes the
// off-diagonal columns of ITS OWN 32 rows (~1MB of __stcs), chunked across
// the main-loop tiles so the store stream drains under rowsum/V-wait/PV.
// This puts store-BW work and tensor/LSU work on every SM simultaneously
// (dedicated zero blocks stole 1 of 2 CTA slots per SM for pure ST work).
#define AP 260
#define VP 264
#define PP 36
#define ATTN_SMEM_F (32 * AP * 2 + 32 * VP + 32 * PP + 32)

extern __shared__ float sm_attn[];

__global__ __launch_bounds__(256)
void attn_mma(const float* __restrict__ Q, const float* __restrict__ K,
              const float* __restrict__ V, float* __restrict__ attn,
              float* __restrict__ O, int Mtot) {
    int b  = blockIdx.x;
    int qs = g_qseg[b], qe = g_qseg[b + 1];
    int ks = g_kseg[b], ke = g_kseg[b + 1];
    int t = threadIdx.x;

    int row0 = qs + (int)blockIdx.y * 32;
    if (row0 >= qe) return;
    int rows = min(32, qe - row0);
    int nk = ke - ks;

    int m4 = Mtot >> 2;
    float4 z4 = make_float4(0.f, 0.f, 0.f, 0.f);

    if (nk == 0) {
        // no keys: zero the full attn rows + O rows
        for (int i = t; i < rows * m4; i += 256) {
            int r = i / m4, c4 = i - r * m4;
            __stcs((float4*)(attn + (size_t)(row0 + r) * Mtot) + c4, z4);
        }
        for (int i = t; i < rows * DIM; i += 256)
            O[(size_t)row0 * DIM + i] = 0.f;
        return;
    }

    int w = t >> 5, lane = t & 31;
    int gid = lane >> 2, tig = lane & 3;

    float* Qs = sm_attn;
    float* Ks = Qs + 32 * AP;
    float* Vs = Ks + 32 * AP;
    float* Ps = Vs + 32 * VP;
    float* rowsum = Ps + 32 * PP;

    int ntiles = (nk + 31) >> 5;

    // per-thread zero-fill coords: thread t owns row (t>>3), c4 = (t&7)+8*i
    int zr = (t >> 3);
    bool zval = zr < rows;
    float* zrow = attn + (size_t)(row0 + zr) * Mtot;
    int zi_total = m4 >> 3;          // 256 when Mtot=8192

    // prologue: Q group, K0 group, V0 group; wait for Q+K0 (V0 in flight)
    for (int i = t; i < 32 * 64; i += 256) {
        int r = i >> 6, c4 = i & 63;
        cp16z(&Qs[r * AP + c4 * 4], &Q[(size_t)(row0 + r) * DIM + c4 * 4], r < rows);
    }
    asm volatile("cp.async.commit_group;\n");
    for (int i = t; i < 32 * 64; i += 256) {
        int r = i >> 6, c4 = i & 63;
        cp16z(&Ks[r * AP + c4 * 4], &K[(size_t)(ks + r) * DIM + c4 * 4], r < nk);
    }
    asm volatile("cp.async.commit_group;\n");
    for (int i = t; i < 32 * 64; i += 256) {
        int r = i >> 6, c4 = i & 63;
        cp16z(&Vs[r * VP + c4 * 4], &V[(size_t)(ks + r) * DIM + c4 * 4], r < nk);
    }
    asm volatile("cp.async.commit_group;\n");
    asm volatile("cp.async.wait_group 1;\n" ::: "memory");
    if (t < 32) rowsum[t] = 0.f;

    int mh  = w & 1;
    int wn0 = (w >> 1) * 8;

    float o_acc[2][4][4] = {};

    for (int kt = 0; kt < ntiles; kt++) {
        int kbase = kt << 5;
        bool more = (kt + 1 < ntiles);
        if (kt > 0)
            asm volatile("cp.async.wait_group 1;\n" ::: "memory");  // K[kt] done
        __syncthreads();                 // K[kt] (and Q) visible to all

        // ---- QK^T, 2-pass: Q hi-only, K split ----
        float sacc[4] = {0.f, 0.f, 0.f, 0.f};
        #pragma unroll
        for (int kk = 0; kk < DIM; kk += 8) {
            unsigned ah[4], bh[2], bl[2];
            int c = kk + tig;
            int mr = mh * 16 + gid;
            ah[0] = f2tf32(Qs[mr * AP + c]);
            ah[1] = f2tf32(Qs[(mr + 8) * AP + c]);
            ah[2] = f2tf32(Qs[mr * AP + c + 4]);
            ah[3] = f2tf32(Qs[(mr + 8) * AP + c + 4]);
            int nr = wn0 + gid;
            split_tf32(Ks[nr * AP + c],     bh[0], bl[0]);
            split_tf32(Ks[nr * AP + c + 4], bh[1], bl[1]);
            mma_tf32(sacc, ah, bh);
            mma_tf32(sacc, ah, bl);
        }
        int kn = kbase + wn0 + 2 * tig;
        float e0 = (kn     < nk) ? __expf(sacc[0] * SCALE) : 0.f;
        float e1 = (kn + 1 < nk) ? __expf(sacc[1] * SCALE) : 0.f;
        float e2 = (kn     < nk) ? __expf(sacc[2] * SCALE) : 0.f;
        float e3 = (kn + 1 < nk) ? __expf(sacc[3] * SCALE) : 0.f;
        int pr = mh * 16 + gid;
        Ps[pr * PP + wn0 + 2 * tig]           = e0;
        Ps[pr * PP + wn0 + 2 * tig + 1]       = e1;
        Ps[(pr + 8) * PP + wn0 + 2 * tig]     = e2;
        Ps[(pr + 8) * PP + wn0 + 2 * tig + 1] = e3;
        __syncthreads();                 // P visible; all Ks reads done

        // prefetch K[kt+1] into Ks (hides under rowsum+PV)
        if (more) {
            int kb2 = kbase + 32;
            for (int i = t; i < 32 * 64; i += 256) {
                int r = i >> 6, c4 = i & 63;
                cp16z(&Ks[r * AP + c4 * 4],
                      &K[(size_t)(ks + kb2 + r) * DIM + c4 * 4], kb2 + r < nk);
            }
            asm volatile("cp.async.commit_group;\n");
        }

        // ---- in-block zero-fill chunk (drains under rowsum/V-wait/PV) ----
        if (zval) {
            int i0 = kt * zi_total / ntiles;
            int i1 = (kt + 1) * zi_total / ntiles;
            for (int i = i0; i < i1; i++) {
                int c4 = (t & 7) + 8 * i;
                int c = c4 * 4;
                if (c + 4 <= ks || c >= ke) {
                    __stcs((float4*)zrow + c4, z4);
                } else if (c < ks || c + 4 > ke) {
                    #pragma unroll
                    for (int e = 0; e < 4; e++) {
                        int cc = c + e;
                        if (cc < ks || cc >= ke) __stcs(zrow + cc, 0.f);
                    }
                }
            }
        }

        // ---- unnormalized attn write + rowsum ----
        #pragma unroll
        for (int i = 0; i < 4; i++) {
            int r = w + i * 8;
            float e = Ps[r * PP + lane];
            float s = e;
            #pragma unroll
            for (int off = 16; off; off >>= 1) s += __shfl_xor_sync(0xFFFFFFFFu, s, off);
            if (lane == 0) rowsum[r] += s;
            if (r < rows && kbase + lane < nk)
                attn[(size_t)(row0 + r) * Mtot + ks + kbase + lane] = e;
        }

        // V[kt] must be complete before PV
        if (more) asm volatile("cp.async.wait_group 1;\n" ::: "memory");
        else      asm volatile("cp.async.wait_group 0;\n" ::: "memory");
        __syncthreads();                 // V[kt] visible to all

        // ---- PV, 2-pass: P hi-only, V split ----
        #pragma unroll
        for (int kk = 0; kk < 32; kk += 8) {
            unsigned pah[2][4];
            int c = kk + tig;
            #pragma unroll
            for (int i = 0; i < 2; i++) {
                int mr = i * 16 + gid;
                pah[i][0] = f2tf32(Ps[mr * PP + c]);
                pah[i][1] = f2tf32(Ps[(mr + 8) * PP + c]);
                pah[i][2] = f2tf32(Ps[mr * PP + c + 4]);
                pah[i][3] = f2tf32(Ps[(mr + 8) * PP + c + 4]);
            }
            #pragma unroll
            for (int j = 0; j < 4; j++) {
                int n = w * 32 + 8 * j + gid;
                unsigned vbh[2], vbl[2];
                split_tf32(Vs[c * VP + n],       vbh[0], vbl[0]);
                split_tf32(Vs[(c + 4) * VP + n], vbh[1], vbl[1]);
                #pragma unroll
                for (int i = 0; i < 2; i++) {
                    mma_tf32(o_acc[i][j], pah[i], vbh);
                    mma_tf32(o_acc[i][j], pah[i], vbl);
                }
            }
        }
        __syncthreads();                 // all Vs reads done

        // prefetch V[kt+1] into Vs (hides under next QK)
        if (more) {
            int kb2 = kbase + 32;
            for (int i = t; i < 32 * 64; i += 256) {
                int r = i >> 6, c4 = i & 63;
                cp16z(&Vs[r * VP + c4 * 4],
                      &V[(size_t)(ks + kb2 + r) * DIM + c4 * 4], kb2 + r < nk);
            }
            asm volatile("cp.async.commit_group;\n");
        }
    }
    __syncthreads();
    if (t < 32) rowsum[t] = (rowsum[t] > 0.f) ? (1.f / rowsum[t]) : 0.f;
    __syncthreads();

    // normalize attn in place (warp-per-row, coalesced)
    #pragma unroll
    for (int i = 0; i < 4; i++) {
        int r = w + i * 8;
        if (r < rows) {
            float inv = rowsum[r];
            size_t base = (size_t)(row0 + r) * Mtot + ks;
            for (int j = lane; j < nk; j += 32) attn[base + j] *= inv;
        }
    }
    #pragma unroll
    for (int i = 0; i < 2; i++) {
        int r = i * 16 + gid;
        if (r < rows) {
            float inv = rowsum[r];
            #pragma unroll
            for (int j = 0; j < 4; j++) {
                int n = w * 32 + 8 * j + 2 * tig;
                *(float2*)&O[(size_t)(row0 + r) * DIM + n] =
                    make_float2(o_acc[i][j][0] * inv, o_acc[i][j][1] * inv);
            }
        }
        int r8 = r + 8;
        if (r8 < rows) {
            float inv = rowsum[r8];
            #pragma unroll
            for (int j = 0; j < 4; j++) {
                int n = w * 32 + 8 * j + 2 * tig;
                *(float2*)&O[(size_t)(row0 + r8) * DIM + n] =
                    make_float2(o_acc[i][j][2] * inv, o_acc[i][j][3] * inv);
            }
        }
    }
}

// ---------------- launch (single stream, no events) -------------------------
extern "C" void kernel_launch(void* const* d_in, const int* in_sizes, int n_in,
                              void* d_out, int out_size) {
    const float* q_feat = (const float*)d_in[0];
    const float* k_feat = (const float*)d_in[1];
    const int*   q_batch = (const int*)d_in[2];
    const int*   k_batch = (const int*)d_in[3];
    const float* Wq = (const float*)d_in[4];
    const float* bq = (const float*)d_in[5];
    const float* Wk = (const float*)d_in[6];
    const float* bk = (const float*)d_in[7];
    const float* Wv = (const float*)d_in[8];
    const float* bv = (const float*)d_in[9];
    const float* Wo = (const float*)d_in[10];
    const float* bo = (const float*)d_in[11];

    int n = in_sizes[0] / DIM;
    int m = in_sizes[1] / DIM;

    float* out      = (float*)d_out;
    float* attended = out;                        // [n, DIM]
    float* attn     = out + (size_t)n * DIM;      // [n, m]

    float *Qd, *Kd, *Vd, *Od;
    cudaGetSymbolAddress((void**)&Qd, g_Q);
    cudaGetSymbolAddress((void**)&Kd, g_K);
    cudaGetSymbolAddress((void**)&Vd, g_V);
    cudaGetSymbolAddress((void**)&Od, g_O);

    const size_t attn_smem = ATTN_SMEM_F * sizeof(float);
    const size_t gemm_smem = GEMM_SMEM_U32 * sizeof(unsigned);
    cudaFuncSetAttribute(attn_mma, cudaFuncAttributeMaxDynamicSharedMemorySize,
                         (int)attn_smem);
    cudaFuncSetAttribute(gemm3_bf16, cudaFuncAttributeMaxDynamicSharedMemorySize,
                         (int)gemm_smem);

    // 1. fused QKV projection (bf16 3-pass GEMM) + segment boundaries
    gemm3_bf16<<<dim3(n / 128, 4, 3), 256, gemm_smem>>>(
        q_feat, k_feat, Wq, bq, Wk, bk, Wv, bv, Qd, Kd, Vd,
        q_batch, k_batch, n, m);
    // 2. attention with in-block off-diagonal zero-fill
    attn_mma<<<dim3(NB, 32), 256, attn_smem>>>(Qd, Kd, Vd, attn, Od, m);
    // 3. output projection
    gemm3_bf16<<<dim3(n / 128, 4, 1), 256, gemm_smem>>>(
        Od, Od, Wo, bo, Wo, bo, Wo, bo, attended, attended, attended,
        nullptr, nullptr, 0, 0);
}